// round 2
// baseline (speedup 1.0000x reference)
#include <cuda_runtime.h>

#define NN 40000
#define NE 640000
#define HID 128

// Scratch (device globals: allocation-free rule)
__device__ float g_h[NN * HID];       // node features
__device__ float g_agg[NN * HID];     // scatter-add accumulator
__device__ float g_t[NN * 256];       // GEMM1 output (pre-BN1)
__device__ float g_z2[NN * HID];      // GEMM2 output (pre-BN2)
__device__ float g_stats1[512];       // BN1 colsum[256], colsumsq[256]
__device__ float g_stats2[256];       // BN2 colsum[128], colsumsq[128]
__device__ float g_bn1A[256], g_bn1B[256];
__device__ float g_bn2A[128], g_bn2B[128];

// ---------------------------------------------------------------------------
// Zero agg + stats buffers. grid 5000 x 256 covers NN*HID/4 float4 exactly.
// ---------------------------------------------------------------------------
__global__ void zero_kernel() {
    int idx = blockIdx.x * 256 + threadIdx.x;
    ((float4*)g_agg)[idx] = make_float4(0.f, 0.f, 0.f, 0.f);
    if (blockIdx.x == 0) {
        if (threadIdx.x < 128)
            ((float4*)g_stats1)[threadIdx.x] = make_float4(0.f, 0.f, 0.f, 0.f);
        else if (threadIdx.x < 192)
            ((float4*)g_stats2)[threadIdx.x - 128] = make_float4(0.f, 0.f, 0.f, 0.f);
    }
}

// ---------------------------------------------------------------------------
// AtomEncoder: h[n] = sum_f atom_emb[f, x[n,f], :]. One warp per node.
// ---------------------------------------------------------------------------
__global__ void atom_kernel(const int* __restrict__ x, const float* __restrict__ aemb) {
    int gwarp = (blockIdx.x * 256 + threadIdx.x) >> 5;
    int lane = threadIdx.x & 31;
    if (gwarp >= NN) return;
    const float4* ae = (const float4*)aemb;
    float4 acc = make_float4(0.f, 0.f, 0.f, 0.f);
#pragma unroll
    for (int f = 0; f < 9; f++) {
        int idx = __ldg(x + gwarp * 9 + f);
        float4 v = ae[(f * 128 + idx) * 32 + lane];
        acc.x += v.x; acc.y += v.y; acc.z += v.z; acc.w += v.w;
    }
    ((float4*)g_h)[gwarp * 32 + lane] = acc;
}

// ---------------------------------------------------------------------------
// Edge kernel: msg = relu(h[src] + bond_embed(edge_attr)); agg[dst] += msg
// Bond table (3x16x128 f32 = 24KB) cached in smem. One warp handles 16 edges.
// Scatter via vector reduction red.global.add.v4.f32 (sm_90+).
// ---------------------------------------------------------------------------
__global__ void edge_kernel(const int* __restrict__ ei, const int* __restrict__ ea,
                            const float* __restrict__ bond) {
    __shared__ float4 bs[1536];  // 3*16*32 float4
    for (int i = threadIdx.x; i < 1536; i += 256) bs[i] = ((const float4*)bond)[i];
    __syncthreads();
    int lane = threadIdx.x & 31;
    int warp = threadIdx.x >> 5;
    int e0 = blockIdx.x * 128 + warp * 16;
    const float4* h4 = (const float4*)g_h;
    for (int j = 0; j < 16; j++) {
        int e = e0 + j;
        int src = __ldg(ei + e);
        int dst = __ldg(ei + NE + e);
        int a0 = __ldg(ea + 3 * e);
        int a1 = __ldg(ea + 3 * e + 1);
        int a2 = __ldg(ea + 3 * e + 2);
        float4 v = h4[src * 32 + lane];
        float4 e0v = bs[a0 * 32 + lane];
        float4 e1v = bs[(16 + a1) * 32 + lane];
        float4 e2v = bs[(32 + a2) * 32 + lane];
        float m0 = fmaxf(v.x + e0v.x + e1v.x + e2v.x, 0.f);
        float m1 = fmaxf(v.y + e0v.y + e1v.y + e2v.y, 0.f);
        float m2 = fmaxf(v.z + e0v.z + e1v.z + e2v.z, 0.f);
        float m3 = fmaxf(v.w + e0v.w + e1v.w + e2v.w, 0.f);
        float* addr = g_agg + dst * HID + lane * 4;
        asm volatile("red.global.add.v4.f32 [%0], {%1,%2,%3,%4};"
                     :: "l"(addr), "f"(m0), "f"(m1), "f"(m2), "f"(m3) : "memory");
    }
}

// ---------------------------------------------------------------------------
// Tiled SGEMM, BM=128 BN=128 BK=16, 256 threads, 8x8 per thread.
// MODE 0: A = (1+eps)*h + agg,          C -> g_t   (+b1), stats -> g_stats1
// MODE 1: A = relu(bn1A*t + bn1B),      C -> g_z2  (+b2), stats -> g_stats2
// MODE 2: A = h,                        C -> outP  (+lin_b), no stats
// ---------------------------------------------------------------------------
template <int KD, int NC, int MODE>
__global__ void __launch_bounds__(256, 2)
gemm_kernel(const float* __restrict__ W, const float* __restrict__ bias,
            const float* __restrict__ epsp, int layer, float* __restrict__ outP) {
    __shared__ float As[16][128];
    __shared__ float4 Bs[16][32];
    __shared__ float Red[16][128];

    int tid = threadIdx.x;
    int tx = tid & 15, ty = tid >> 4;
    int row0 = blockIdx.x * 128;
    int n0 = blockIdx.y * 128;

    float acc[8][8];
#pragma unroll
    for (int i = 0; i < 8; i++)
#pragma unroll
        for (int j = 0; j < 8; j++) acc[i][j] = 0.f;

    float epsv = 0.f;
    if (MODE == 0) epsv = 1.f + __ldg(epsp + layer);

    for (int k0 = 0; k0 < KD; k0 += 16) {
#pragma unroll
        for (int p = 0; p < 2; p++) {
            int fi = tid + p * 256;
            int r = fi >> 2, kq = fi & 3;
            int grow = row0 + r;
            float4 v = make_float4(0.f, 0.f, 0.f, 0.f);
            if (grow < NN) {
                int gi = grow * (KD / 4) + (k0 >> 2) + kq;
                if (MODE == 0) {
                    float4 a = ((const float4*)g_h)[gi];
                    float4 b = ((const float4*)g_agg)[gi];
                    v.x = fmaf(epsv, a.x, b.x);
                    v.y = fmaf(epsv, a.y, b.y);
                    v.z = fmaf(epsv, a.z, b.z);
                    v.w = fmaf(epsv, a.w, b.w);
                } else if (MODE == 1) {
                    float4 a = ((const float4*)g_t)[gi];
                    int c = k0 + kq * 4;
                    v.x = fmaxf(fmaf(g_bn1A[c + 0], a.x, g_bn1B[c + 0]), 0.f);
                    v.y = fmaxf(fmaf(g_bn1A[c + 1], a.y, g_bn1B[c + 1]), 0.f);
                    v.z = fmaxf(fmaf(g_bn1A[c + 2], a.z, g_bn1B[c + 2]), 0.f);
                    v.w = fmaxf(fmaf(g_bn1A[c + 3], a.w, g_bn1B[c + 3]), 0.f);
                } else {
                    v = ((const float4*)g_h)[gi];
                }
            }
            As[kq * 4 + 0][r] = v.x;
            As[kq * 4 + 1][r] = v.y;
            As[kq * 4 + 2][r] = v.z;
            As[kq * 4 + 3][r] = v.w;
        }
#pragma unroll
        for (int p = 0; p < 2; p++) {
            int fi = tid + p * 256;
            int r = fi >> 5, c4 = fi & 31;
            Bs[r][c4] = ((const float4*)W)[((k0 + r) * NC + n0) / 4 + c4];
        }
        __syncthreads();
#pragma unroll
        for (int kk = 0; kk < 16; kk++) {
            float4 a0 = *(const float4*)&As[kk][ty * 8];
            float4 a1 = *(const float4*)&As[kk][ty * 8 + 4];
            float4 b0 = Bs[kk][tx * 2];
            float4 b1 = Bs[kk][tx * 2 + 1];
            float av[8] = {a0.x, a0.y, a0.z, a0.w, a1.x, a1.y, a1.z, a1.w};
            float bv[8] = {b0.x, b0.y, b0.z, b0.w, b1.x, b1.y, b1.z, b1.w};
#pragma unroll
            for (int i = 0; i < 8; i++)
#pragma unroll
                for (int j = 0; j < 8; j++)
                    acc[i][j] = fmaf(av[i], bv[j], acc[i][j]);
        }
        __syncthreads();
    }

    float bsv[8];
#pragma unroll
    for (int j = 0; j < 8; j++) bsv[j] = __ldg(bias + n0 + tx * 8 + j);

    float s[8], q[8];
#pragma unroll
    for (int j = 0; j < 8; j++) { s[j] = 0.f; q[j] = 0.f; }

#pragma unroll
    for (int i = 0; i < 8; i++) {
        int grow = row0 + ty * 8 + i;
        if (grow < NN) {
            float c[8];
#pragma unroll
            for (int j = 0; j < 8; j++) {
                c[j] = acc[i][j] + bsv[j];
                s[j] += c[j];
                q[j] += c[j] * c[j];
            }
            float4* dstp;
            if (MODE == 0)      dstp = (float4*)(g_t + grow * 256 + n0 + tx * 8);
            else if (MODE == 1) dstp = (float4*)(g_z2 + grow * 128 + tx * 8);
            else                dstp = (float4*)(outP + grow * 256 + n0 + tx * 8);
            dstp[0] = make_float4(c[0], c[1], c[2], c[3]);
            dstp[1] = make_float4(c[4], c[5], c[6], c[7]);
        }
    }

    if (MODE != 2) {
        float* ST = (MODE == 0) ? g_stats1 : g_stats2;
#pragma unroll
        for (int j = 0; j < 8; j++) Red[ty][tx * 8 + j] = s[j];
        __syncthreads();
        if (tid < 128) {
            float tot = 0.f;
#pragma unroll
            for (int t = 0; t < 16; t++) tot += Red[t][tid];
            atomicAdd(&ST[n0 + tid], tot);
        }
        __syncthreads();
#pragma unroll
        for (int j = 0; j < 8; j++) Red[ty][tx * 8 + j] = q[j];
        __syncthreads();
        if (tid < 128) {
            float tot = 0.f;
#pragma unroll
            for (int t = 0; t < 16; t++) tot += Red[t][tid];
            atomicAdd(&ST[NC + n0 + tid], tot);
        }
    }
}

// ---------------------------------------------------------------------------
// Finalize BN: scale = gamma*rsqrt(var+eps), shift = beta - mu*scale
// ---------------------------------------------------------------------------
__global__ void finalize_bn(const float* __restrict__ gamma, const float* __restrict__ beta,
                            int which, int nc) {
    int c = threadIdx.x;
    if (c >= nc) return;
    const float* ST = (which == 0) ? g_stats1 : g_stats2;
    float mu = ST[c] * (1.f / NN);
    float var = ST[nc + c] * (1.f / NN) - mu * mu;
    float inv = rsqrtf(var + 1e-5f);
    float sc = gamma[c] * inv;
    float sh = beta[c] - mu * sc;
    if (which == 0) { g_bn1A[c] = sc; g_bn1B[c] = sh; }
    else            { g_bn2A[c] = sc; g_bn2B[c] = sh; }
}

// ---------------------------------------------------------------------------
// Apply BN2 (+ optional relu): h = act(bn2A*z2 + bn2B)
// ---------------------------------------------------------------------------
__global__ void bn_apply_kernel(int do_relu) {
    int idx = blockIdx.x * 256 + threadIdx.x;  // float4 index over NN*32
    float4 v = ((const float4*)g_z2)[idx];
    int c = (idx & 31) * 4;
    v.x = fmaf(g_bn2A[c + 0], v.x, g_bn2B[c + 0]);
    v.y = fmaf(g_bn2A[c + 1], v.y, g_bn2B[c + 1]);
    v.z = fmaf(g_bn2A[c + 2], v.z, g_bn2B[c + 2]);
    v.w = fmaf(g_bn2A[c + 3], v.w, g_bn2B[c + 3]);
    if (do_relu) {
        v.x = fmaxf(v.x, 0.f); v.y = fmaxf(v.y, 0.f);
        v.z = fmaxf(v.z, 0.f); v.w = fmaxf(v.w, 0.f);
    }
    ((float4*)g_h)[idx] = v;
}

// ---------------------------------------------------------------------------
extern "C" void kernel_launch(void* const* d_in, const int* in_sizes, int n_in,
                              void* d_out, int out_size) {
    const int*   x    = (const int*)d_in[0];
    const int*   ei   = (const int*)d_in[1];
    const int*   ea   = (const int*)d_in[2];
    const float* aemb = (const float*)d_in[3];
    const float* bemb = (const float*)d_in[4];
    const float* eps  = (const float*)d_in[5];
    const float* w1   = (const float*)d_in[6];
    const float* b1   = (const float*)d_in[7];
    const float* bn1g = (const float*)d_in[8];
    const float* bn1b = (const float*)d_in[9];
    const float* w2   = (const float*)d_in[10];
    const float* b2   = (const float*)d_in[11];
    const float* bng  = (const float*)d_in[12];
    const float* bnb  = (const float*)d_in[13];
    const float* linw = (const float*)d_in[14];
    const float* linb = (const float*)d_in[15];

    atom_kernel<<<5000, 256>>>(x, aemb);
    for (int l = 0; l < 5; l++) {
        zero_kernel<<<5000, 256>>>();
        edge_kernel<<<5000, 256>>>(ei, ea, bemb + l * 3 * 16 * 128);
        gemm_kernel<128, 256, 0><<<dim3(313, 2), 256>>>(w1 + l * 128 * 256, b1 + l * 256, eps, l, nullptr);
        finalize_bn<<<1, 256>>>(bn1g + l * 256, bn1b + l * 256, 0, 256);
        gemm_kernel<256, 128, 1><<<dim3(313, 1), 256>>>(w2 + l * 256 * 128, b2 + l * 128, nullptr, 0, nullptr);
        finalize_bn<<<1, 128>>>(bng + l * 128, bnb + l * 128, 1, 128);
        bn_apply_kernel<<<5000, 256>>>(l < 4 ? 1 : 0);
    }
    gemm_kernel<128, 256, 2><<<dim3(313, 2), 256>>>(linw, linb, nullptr, 0, (float*)d_out);
}

// round 3
// speedup vs baseline: 1.0530x; 1.0530x over previous
#include <cuda_runtime.h>

#define NN 40000
#define NE 640000
#define HID 128

// Scratch (device globals: allocation-free rule)
__device__ float g_h[NN * HID];
__device__ float g_agg[NN * HID];
__device__ float g_t[NN * 256];
__device__ float g_z2[NN * HID];
__device__ float g_stats1[512];
__device__ float g_stats2[256];
__device__ float g_bn1A[256], g_bn1B[256];
__device__ float g_bn2A[128], g_bn2B[128];

__device__ __forceinline__ void ffma2(unsigned long long& d, unsigned long long a,
                                      unsigned long long b) {
    asm("fma.rn.f32x2 %0, %1, %2, %0;" : "+l"(d) : "l"(a), "l"(b));
}
__device__ __forceinline__ unsigned long long dup2(float x) {
    unsigned long long r;
    asm("mov.b64 %0, {%1, %1};" : "=l"(r) : "f"(x));
    return r;
}

// ---------------------------------------------------------------------------
__global__ void zero_kernel() {
    int idx = blockIdx.x * 256 + threadIdx.x;
    ((float4*)g_agg)[idx] = make_float4(0.f, 0.f, 0.f, 0.f);
    if (blockIdx.x == 0) {
        if (threadIdx.x < 128)
            ((float4*)g_stats1)[threadIdx.x] = make_float4(0.f, 0.f, 0.f, 0.f);
        else if (threadIdx.x < 192)
            ((float4*)g_stats2)[threadIdx.x - 128] = make_float4(0.f, 0.f, 0.f, 0.f);
    }
}

// ---------------------------------------------------------------------------
__global__ void atom_kernel(const int* __restrict__ x, const float* __restrict__ aemb) {
    int gwarp = (blockIdx.x * 256 + threadIdx.x) >> 5;
    int lane = threadIdx.x & 31;
    if (gwarp >= NN) return;
    const float4* ae = (const float4*)aemb;
    float4 acc = make_float4(0.f, 0.f, 0.f, 0.f);
#pragma unroll
    for (int f = 0; f < 9; f++) {
        int idx = __ldg(x + gwarp * 9 + f);
        float4 v = ae[(f * 128 + idx) * 32 + lane];
        acc.x += v.x; acc.y += v.y; acc.z += v.z; acc.w += v.w;
    }
    ((float4*)g_h)[gwarp * 32 + lane] = acc;
}

// ---------------------------------------------------------------------------
__global__ void edge_kernel(const int* __restrict__ ei, const int* __restrict__ ea,
                            const float* __restrict__ bond) {
    __shared__ float4 bs[1536];  // 3*16*32 float4
    for (int i = threadIdx.x; i < 1536; i += 256) bs[i] = ((const float4*)bond)[i];
    __syncthreads();
    int lane = threadIdx.x & 31;
    int warp = threadIdx.x >> 5;
    int e0 = blockIdx.x * 128 + warp * 16;
    const float4* h4 = (const float4*)g_h;
#pragma unroll 4
    for (int j = 0; j < 16; j++) {
        int e = e0 + j;
        int src = __ldg(ei + e);
        int dst = __ldg(ei + NE + e);
        int a0 = __ldg(ea + 3 * e);
        int a1 = __ldg(ea + 3 * e + 1);
        int a2 = __ldg(ea + 3 * e + 2);
        float4 v = h4[src * 32 + lane];
        float4 e0v = bs[a0 * 32 + lane];
        float4 e1v = bs[(16 + a1) * 32 + lane];
        float4 e2v = bs[(32 + a2) * 32 + lane];
        float m0 = fmaxf(v.x + e0v.x + e1v.x + e2v.x, 0.f);
        float m1 = fmaxf(v.y + e0v.y + e1v.y + e2v.y, 0.f);
        float m2 = fmaxf(v.z + e0v.z + e1v.z + e2v.z, 0.f);
        float m3 = fmaxf(v.w + e0v.w + e1v.w + e2v.w, 0.f);
        float* addr = g_agg + dst * HID + lane * 4;
        asm volatile("red.global.add.v4.f32 [%0], {%1,%2,%3,%4};"
                     :: "l"(addr), "f"(m0), "f"(m1), "f"(m2), "f"(m3) : "memory");
    }
}

// ---------------------------------------------------------------------------
// A-tile fragment loader (per-mode fused prologue)
// ---------------------------------------------------------------------------
template <int KD, int MODE>
__device__ __forceinline__ float4 gemm_loadA(int growA, int kqA, int k0, float epsv) {
    float4 v = make_float4(0.f, 0.f, 0.f, 0.f);
    if (growA < NN) {
        int gi = growA * (KD / 4) + (k0 >> 2) + kqA;
        if (MODE == 0) {
            float4 a = ((const float4*)g_h)[gi];
            float4 b = ((const float4*)g_agg)[gi];
            v.x = fmaf(epsv, a.x, b.x);
            v.y = fmaf(epsv, a.y, b.y);
            v.z = fmaf(epsv, a.z, b.z);
            v.w = fmaf(epsv, a.w, b.w);
        } else if (MODE == 1) {
            float4 a = ((const float4*)g_t)[gi];
            int c = k0 + kqA * 4;
            v.x = fmaxf(fmaf(g_bn1A[c + 0], a.x, g_bn1B[c + 0]), 0.f);
            v.y = fmaxf(fmaf(g_bn1A[c + 1], a.y, g_bn1B[c + 1]), 0.f);
            v.z = fmaxf(fmaf(g_bn1A[c + 2], a.z, g_bn1B[c + 2]), 0.f);
            v.w = fmaxf(fmaf(g_bn1A[c + 3], a.w, g_bn1B[c + 3]), 0.f);
        } else {
            v = ((const float4*)g_h)[gi];
        }
    }
    return v;
}

// ---------------------------------------------------------------------------
// SGEMM with packed fp32x2 FMAs. BM=128 BN=128 BK=8, 256 threads, 8x8/thread
// (accumulators held as 8x4 f32x2 pairs). Double-buffered smem, reg prefetch.
// A stored DUPLICATED in smem as (a,a) 64-bit words so FFMA2 needs no packing.
// MODE 0: A=(1+eps)*h+agg -> g_t (+b1), stats1.  MODE 1: A=relu(bn1(t)) ->
// g_z2 (+b2), stats2.  MODE 2: A=h -> out (+lin_b).
// ---------------------------------------------------------------------------
template <int KD, int NC, int MODE>
__global__ void __launch_bounds__(256, 2)
gemm_kernel(const float* __restrict__ W, const float* __restrict__ bias,
            const float* __restrict__ epsp, int layer, float* __restrict__ outP) {
    __shared__ unsigned long long As2[2][8][130];  // [stage][k][row] dup pairs
    __shared__ float Bs[2][8][132];                // [stage][k][col]
    __shared__ float Red[16][128];

    int tid = threadIdx.x;
    int tx = tid & 15, ty = tid >> 4;
    int row0 = blockIdx.x * 128;
    int n0 = blockIdx.y * 128;

    int rA = tid >> 1, kqA = tid & 1;  // A loader: 1 float4 per thread per tile
    int rB = tid >> 5, cB = tid & 31;  // B loader: 1 float4 per thread per tile
    int growA = row0 + rA;

    float epsv = (MODE == 0) ? 1.f + __ldg(epsp + layer) : 0.f;

    unsigned long long acc[8][4];
#pragma unroll
    for (int i = 0; i < 8; i++)
#pragma unroll
        for (int j = 0; j < 4; j++) acc[i][j] = 0ull;

    constexpr int T = KD / 8;
    const float4* W4 = (const float4*)W;

    // prologue: tile 0
    float4 va = gemm_loadA<KD, MODE>(growA, kqA, 0, epsv);
    float4 vb = W4[(0 + rB) * (NC / 4) + (n0 >> 2) + cB];
    As2[0][kqA * 4 + 0][rA] = dup2(va.x);
    As2[0][kqA * 4 + 1][rA] = dup2(va.y);
    As2[0][kqA * 4 + 2][rA] = dup2(va.z);
    As2[0][kqA * 4 + 3][rA] = dup2(va.w);
    *(float4*)&Bs[0][rB][cB * 4] = vb;
    __syncthreads();

#pragma unroll 2
    for (int t = 0; t < T; t++) {
        int st = t & 1;
        if (t + 1 < T) {
            va = gemm_loadA<KD, MODE>(growA, kqA, (t + 1) * 8, epsv);
            vb = W4[((t + 1) * 8 + rB) * (NC / 4) + (n0 >> 2) + cB];
        }
#pragma unroll
        for (int kk = 0; kk < 8; kk++) {
            unsigned long long ad[8], bp[4];
            const unsigned long long* aP = &As2[st][kk][ty * 8];
            const unsigned long long* bP = (const unsigned long long*)&Bs[st][kk][tx * 8];
#pragma unroll
            for (int i = 0; i < 8; i++) ad[i] = aP[i];
#pragma unroll
            for (int j = 0; j < 4; j++) bp[j] = bP[j];
#pragma unroll
            for (int i = 0; i < 8; i++)
#pragma unroll
                for (int j = 0; j < 4; j++) ffma2(acc[i][j], ad[i], bp[j]);
        }
        if (t + 1 < T) {
            As2[st ^ 1][kqA * 4 + 0][rA] = dup2(va.x);
            As2[st ^ 1][kqA * 4 + 1][rA] = dup2(va.y);
            As2[st ^ 1][kqA * 4 + 2][rA] = dup2(va.z);
            As2[st ^ 1][kqA * 4 + 3][rA] = dup2(va.w);
            *(float4*)&Bs[st ^ 1][rB][cB * 4] = vb;
            __syncthreads();
        }
    }

    float bsv[8];
#pragma unroll
    for (int j = 0; j < 8; j++) bsv[j] = __ldg(bias + n0 + tx * 8 + j);

    float s[8], q[8];
#pragma unroll
    for (int j = 0; j < 8; j++) { s[j] = 0.f; q[j] = 0.f; }

#pragma unroll
    for (int i = 0; i < 8; i++) {
        int grow = row0 + ty * 8 + i;
        if (grow < NN) {
            float c[8];
#pragma unroll
            for (int j4 = 0; j4 < 4; j4++) {
                unsigned long long v = acc[i][j4];
                c[2 * j4 + 0] = __uint_as_float((unsigned)v) + bsv[2 * j4 + 0];
                c[2 * j4 + 1] = __uint_as_float((unsigned)(v >> 32)) + bsv[2 * j4 + 1];
            }
#pragma unroll
            for (int j = 0; j < 8; j++) { s[j] += c[j]; q[j] += c[j] * c[j]; }
            float4* dstp;
            if (MODE == 0)      dstp = (float4*)(g_t + grow * 256 + n0 + tx * 8);
            else if (MODE == 1) dstp = (float4*)(g_z2 + grow * 128 + tx * 8);
            else                dstp = (float4*)(outP + grow * 256 + n0 + tx * 8);
            dstp[0] = make_float4(c[0], c[1], c[2], c[3]);
            dstp[1] = make_float4(c[4], c[5], c[6], c[7]);
        }
    }

    if (MODE != 2) {
        float* ST = (MODE == 0) ? g_stats1 : g_stats2;
#pragma unroll
        for (int j = 0; j < 8; j++) Red[ty][tx * 8 + j] = s[j];
        __syncthreads();
        if (tid < 128) {
            float tot = 0.f;
#pragma unroll
            for (int t = 0; t < 16; t++) tot += Red[t][tid];
            atomicAdd(&ST[n0 + tid], tot);
        }
        __syncthreads();
#pragma unroll
        for (int j = 0; j < 8; j++) Red[ty][tx * 8 + j] = q[j];
        __syncthreads();
        if (tid < 128) {
            float tot = 0.f;
#pragma unroll
            for (int t = 0; t < 16; t++) tot += Red[t][tid];
            atomicAdd(&ST[NC + n0 + tid], tot);
        }
    }
}

// ---------------------------------------------------------------------------
__global__ void finalize_bn(const float* __restrict__ gamma, const float* __restrict__ beta,
                            int which, int nc) {
    int c = threadIdx.x;
    if (c >= nc) return;
    const float* ST = (which == 0) ? g_stats1 : g_stats2;
    float mu = ST[c] * (1.f / NN);
    float var = ST[nc + c] * (1.f / NN) - mu * mu;
    float inv = rsqrtf(var + 1e-5f);
    float sc = gamma[c] * inv;
    float sh = beta[c] - mu * sc;
    if (which == 0) { g_bn1A[c] = sc; g_bn1B[c] = sh; }
    else            { g_bn2A[c] = sc; g_bn2B[c] = sh; }
}

// ---------------------------------------------------------------------------
__global__ void bn_apply_kernel(int do_relu) {
    int idx = blockIdx.x * 256 + threadIdx.x;
    float4 v = ((const float4*)g_z2)[idx];
    int c = (idx & 31) * 4;
    v.x = fmaf(g_bn2A[c + 0], v.x, g_bn2B[c + 0]);
    v.y = fmaf(g_bn2A[c + 1], v.y, g_bn2B[c + 1]);
    v.z = fmaf(g_bn2A[c + 2], v.z, g_bn2B[c + 2]);
    v.w = fmaf(g_bn2A[c + 3], v.w, g_bn2B[c + 3]);
    if (do_relu) {
        v.x = fmaxf(v.x, 0.f); v.y = fmaxf(v.y, 0.f);
        v.z = fmaxf(v.z, 0.f); v.w = fmaxf(v.w, 0.f);
    }
    ((float4*)g_h)[idx] = v;
}

// ---------------------------------------------------------------------------
extern "C" void kernel_launch(void* const* d_in, const int* in_sizes, int n_in,
                              void* d_out, int out_size) {
    const int*   x    = (const int*)d_in[0];
    const int*   ei   = (const int*)d_in[1];
    const int*   ea   = (const int*)d_in[2];
    const float* aemb = (const float*)d_in[3];
    const float* bemb = (const float*)d_in[4];
    const float* eps  = (const float*)d_in[5];
    const float* w1   = (const float*)d_in[6];
    const float* b1   = (const float*)d_in[7];
    const float* bn1g = (const float*)d_in[8];
    const float* bn1b = (const float*)d_in[9];
    const float* w2   = (const float*)d_in[10];
    const float* b2   = (const float*)d_in[11];
    const float* bng  = (const float*)d_in[12];
    const float* bnb  = (const float*)d_in[13];
    const float* linw = (const float*)d_in[14];
    const float* linb = (const float*)d_in[15];

    atom_kernel<<<5000, 256>>>(x, aemb);
    for (int l = 0; l < 5; l++) {
        zero_kernel<<<5000, 256>>>();
        edge_kernel<<<5000, 256>>>(ei, ea, bemb + l * 3 * 16 * 128);
        gemm_kernel<128, 256, 0><<<dim3(313, 2), 256>>>(w1 + l * 128 * 256, b1 + l * 256, eps, l, nullptr);
        finalize_bn<<<1, 256>>>(bn1g + l * 256, bn1b + l * 256, 0, 256);
        gemm_kernel<256, 128, 1><<<dim3(313, 1), 256>>>(w2 + l * 256 * 128, b2 + l * 128, nullptr, 0, nullptr);
        finalize_bn<<<1, 128>>>(bng + l * 128, bnb + l * 128, 1, 128);
        bn_apply_kernel<<<5000, 256>>>(l < 4 ? 1 : 0);
    }
    gemm_kernel<128, 256, 2><<<dim3(313, 2), 256>>>(linw, linb, nullptr, 0, (float*)d_out);
}

// round 12
// speedup vs baseline: 1.4012x; 1.3307x over previous
#include <cuda_runtime.h>
#include <cuda_bf16.h>
#include <mma.h>
#include <cstdint>

using namespace nvcuda;

#define NN 40000
#define NE 640000

// ------------------------- scratch (device globals) -------------------------
__device__ float g_h[NN * 128];
__device__ float g_agg[NN * 128];
__device__ float g_t[NN * 256];
__device__ float g_z2[NN * 128];
__device__ float g_stats1[512];
__device__ float g_stats2[256];
__device__ float g_bn1A[256], g_bn1B[256];
__device__ float g_bn2A[128], g_bn2B[128];
// bf16 hi/lo weights, natural [k][n] layout (row-major matrix_b)
__device__ uint4 g_w1h[5 * 128 * 256 / 8], g_w1l[5 * 128 * 256 / 8];
__device__ uint4 g_w2h[5 * 256 * 128 / 8], g_w2l[5 * 256 * 128 / 8];
__device__ uint4 g_linh[128 * 256 / 8],    g_linl[128 * 256 / 8];

// ------------------------------ small kernels ------------------------------
__global__ void zero_kernel() {
    int idx = blockIdx.x * 256 + threadIdx.x;
    ((float4*)g_agg)[idx] = make_float4(0.f, 0.f, 0.f, 0.f);
    if (blockIdx.x == 0) {
        if (threadIdx.x < 128)
            ((float4*)g_stats1)[threadIdx.x] = make_float4(0.f, 0.f, 0.f, 0.f);
        else if (threadIdx.x < 192)
            ((float4*)g_stats2)[threadIdx.x - 128] = make_float4(0.f, 0.f, 0.f, 0.f);
    }
}

__global__ void atom_kernel(const int* __restrict__ x, const float* __restrict__ aemb) {
    int gwarp = (blockIdx.x * 256 + threadIdx.x) >> 5;
    int lane = threadIdx.x & 31;
    if (gwarp >= NN) return;
    const float4* ae = (const float4*)aemb;
    float4 acc = make_float4(0.f, 0.f, 0.f, 0.f);
#pragma unroll
    for (int f = 0; f < 9; f++) {
        int idx = __ldg(x + gwarp * 9 + f);
        float4 v = ae[(f * 128 + idx) * 32 + lane];
        acc.x += v.x; acc.y += v.y; acc.z += v.z; acc.w += v.w;
    }
    ((float4*)g_h)[gwarp * 32 + lane] = acc;
}

__global__ void edge_kernel(const int* __restrict__ ei, const int* __restrict__ ea,
                            const float* __restrict__ bond) {
    __shared__ float4 bs[1536];
    for (int i = threadIdx.x; i < 1536; i += 256) bs[i] = ((const float4*)bond)[i];
    __syncthreads();
    int lane = threadIdx.x & 31;
    int warp = threadIdx.x >> 5;
    int e0 = blockIdx.x * 128 + warp * 16;
    const float4* h4 = (const float4*)g_h;
#pragma unroll 4
    for (int j = 0; j < 16; j++) {
        int e = e0 + j;
        int src = __ldg(ei + e);
        int dst = __ldg(ei + NE + e);
        int a0 = __ldg(ea + 3 * e);
        int a1 = __ldg(ea + 3 * e + 1);
        int a2 = __ldg(ea + 3 * e + 2);
        float4 v = h4[src * 32 + lane];
        float4 e0v = bs[a0 * 32 + lane];
        float4 e1v = bs[(16 + a1) * 32 + lane];
        float4 e2v = bs[(32 + a2) * 32 + lane];
        float m0 = fmaxf(v.x + e0v.x + e1v.x + e2v.x, 0.f);
        float m1 = fmaxf(v.y + e0v.y + e1v.y + e2v.y, 0.f);
        float m2 = fmaxf(v.z + e0v.z + e1v.z + e2v.z, 0.f);
        float m3 = fmaxf(v.w + e0v.w + e1v.w + e2v.w, 0.f);
        float* addr = g_agg + dst * 128 + lane * 4;
        asm volatile("red.global.add.v4.f32 [%0], {%1,%2,%3,%4};"
                     :: "l"(addr), "f"(m0), "f"(m1), "f"(m2), "f"(m3) : "memory");
    }
}

// Pre-convert all weights to bf16 hi/lo (keep [k][n] layout).
__global__ void convert_kernel(const float* __restrict__ w1, const float* __restrict__ w2,
                               const float* __restrict__ lin) {
    int idx = blockIdx.x * 256 + threadIdx.x;
    if (idx < 5 * 128 * 256) {
        float v = w1[idx];
        __nv_bfloat16 h = __float2bfloat16_rn(v);
        ((__nv_bfloat16*)g_w1h)[idx] = h;
        ((__nv_bfloat16*)g_w1l)[idx] = __float2bfloat16_rn(v - __bfloat162float(h));
        v = w2[idx];
        h = __float2bfloat16_rn(v);
        ((__nv_bfloat16*)g_w2h)[idx] = h;
        ((__nv_bfloat16*)g_w2l)[idx] = __float2bfloat16_rn(v - __bfloat162float(h));
    }
    if (idx < 128 * 256) {
        float v = lin[idx];
        __nv_bfloat16 h = __float2bfloat16_rn(v);
        ((__nv_bfloat16*)g_linh)[idx] = h;
        ((__nv_bfloat16*)g_linl)[idx] = __float2bfloat16_rn(v - __bfloat162float(h));
    }
}

// Column sums / sumsq. NC=256: g_t -> g_stats1. NC=128: g_z2 -> g_stats2.
template <int NC>
__global__ void stats_kernel() {
    const float* src = (NC == 256) ? g_t : g_z2;
    float* st = (NC == 256) ? g_stats1 : g_stats2;
    int col = threadIdx.x;
    int r0 = blockIdx.x * 128;
    int rend = min(r0 + 128, NN);
    float s = 0.f, q = 0.f;
    for (int r = r0; r < rend; r++) {
        float v = src[(size_t)r * NC + col];
        s += v;
        q = fmaf(v, v, q);
    }
    atomicAdd(&st[col], s);
    atomicAdd(&st[NC + col], q);
}

__global__ void finalize_bn(const float* __restrict__ gamma, const float* __restrict__ beta,
                            int which, int nc) {
    int c = threadIdx.x;
    if (c >= nc) return;
    const float* ST = (which == 0) ? g_stats1 : g_stats2;
    float mu = ST[c] * (1.f / NN);
    float var = ST[nc + c] * (1.f / NN) - mu * mu;
    float inv = rsqrtf(var + 1e-5f);
    float sc = gamma[c] * inv;
    float sh = beta[c] - mu * sc;
    if (which == 0) { g_bn1A[c] = sc; g_bn1B[c] = sh; }
    else            { g_bn2A[c] = sc; g_bn2B[c] = sh; }
}

__global__ void bn_apply_kernel(int do_relu) {
    int idx = blockIdx.x * 256 + threadIdx.x;
    float4 v = ((const float4*)g_z2)[idx];
    int c = (idx & 31) * 4;
    v.x = fmaf(g_bn2A[c + 0], v.x, g_bn2B[c + 0]);
    v.y = fmaf(g_bn2A[c + 1], v.y, g_bn2B[c + 1]);
    v.z = fmaf(g_bn2A[c + 2], v.z, g_bn2B[c + 2]);
    v.w = fmaf(g_bn2A[c + 3], v.w, g_bn2B[c + 3]);
    if (do_relu) {
        v.x = fmaxf(v.x, 0.f); v.y = fmaxf(v.y, 0.f);
        v.z = fmaxf(v.z, 0.f); v.w = fmaxf(v.w, 0.f);
    }
    ((float4*)g_h)[idx] = v;
}

__global__ void bias_out_kernel(float* __restrict__ out, const float* __restrict__ linb) {
    int idx = blockIdx.x * 256 + threadIdx.x;  // float4 over NN*256/4
    float4 v = ((float4*)out)[idx];
    int c = (idx & 63) * 4;
    v.x += __ldg(linb + c + 0);
    v.y += __ldg(linb + c + 1);
    v.z += __ldg(linb + c + 2);
    v.w += __ldg(linb + c + 3);
    ((float4*)out)[idx] = v;
}

// ----------------------- bf16x3 WMMA GEMM (tensor pipe) ---------------------
// 128x128 tile/CTA, BK=32 double-buffered. 8 warps, warp tile 64x32.
// MODE 0: A=(1+eps)*h+agg, B=w1  -> g_t    (bias dropped: BN-invariant)
// MODE 1: A=relu(bn1(g_t)), B=w2 -> g_z2   (bias dropped: BN-invariant)
// MODE 2: A=h,              B=lin -> out   (lin_b added by bias_out_kernel)
template <int KD, int MODE>
__device__ __forceinline__ float4 loadA(int grow, int k, float epsv) {
    float4 v = make_float4(0.f, 0.f, 0.f, 0.f);
    if (grow < NN) {
        int gi = (grow * KD + k) >> 2;
        if (MODE == 0) {
            float4 a = ((const float4*)g_h)[gi];
            float4 b = ((const float4*)g_agg)[gi];
            v.x = fmaf(epsv, a.x, b.x);
            v.y = fmaf(epsv, a.y, b.y);
            v.z = fmaf(epsv, a.z, b.z);
            v.w = fmaf(epsv, a.w, b.w);
        } else if (MODE == 1) {
            float4 a = ((const float4*)g_t)[gi];
            v.x = fmaxf(fmaf(g_bn1A[k + 0], a.x, g_bn1B[k + 0]), 0.f);
            v.y = fmaxf(fmaf(g_bn1A[k + 1], a.y, g_bn1B[k + 1]), 0.f);
            v.z = fmaxf(fmaf(g_bn1A[k + 2], a.z, g_bn1B[k + 2]), 0.f);
            v.w = fmaxf(fmaf(g_bn1A[k + 3], a.w, g_bn1B[k + 3]), 0.f);
        } else {
            v = ((const float4*)g_h)[gi];
        }
    }
    return v;
}

__device__ __forceinline__ void cvt_split4(float4 v, uint2& hi, uint2& lo) {
    __nv_bfloat16 hx = __float2bfloat16_rn(v.x), hy = __float2bfloat16_rn(v.y);
    __nv_bfloat16 hz = __float2bfloat16_rn(v.z), hw = __float2bfloat16_rn(v.w);
    __nv_bfloat162 h01, h23, l01, l23;
    h01.x = hx; h01.y = hy; h23.x = hz; h23.y = hw;
    l01.x = __float2bfloat16_rn(v.x - __bfloat162float(hx));
    l01.y = __float2bfloat16_rn(v.y - __bfloat162float(hy));
    l23.x = __float2bfloat16_rn(v.z - __bfloat162float(hz));
    l23.y = __float2bfloat16_rn(v.w - __bfloat162float(hw));
    hi.x = *(uint32_t*)&h01; hi.y = *(uint32_t*)&h23;
    lo.x = *(uint32_t*)&l01; lo.y = *(uint32_t*)&l23;
}

// smem layout (bytes): Ahi[2][128][40] | Alo[2][128][40] | Bhi[2][32][136] | Blo[2][32][136]
#define AHo 0
#define ALo 20480
#define BHo 40960
#define BLo 58368
#define ASTG 10240
#define BSTG 8704
#define GEMM_SMEM_BYTES 75776

template <int KD, int MODE>
__global__ void __launch_bounds__(256)
mma_gemm(int layer, float* __restrict__ outP, const float* __restrict__ epsp) {
    extern __shared__ char sm[];
    constexpr int NC = (MODE == 1) ? 128 : 256;
    constexpr int NCH = KD / 32;

    int tid = threadIdx.x;
    int row0 = blockIdx.x * 128;
    int n0 = blockIdx.y * 128;

    float epsv = (MODE == 0) ? 1.f + __ldg(epsp + layer) : 0.f;
    const __nv_bfloat16* WH =
        (MODE == 0) ? (const __nv_bfloat16*)g_w1h + layer * 32768
      : (MODE == 1) ? (const __nv_bfloat16*)g_w2h + layer * 32768
                    : (const __nv_bfloat16*)g_linh;
    const __nv_bfloat16* WL =
        (MODE == 0) ? (const __nv_bfloat16*)g_w1l + layer * 32768
      : (MODE == 1) ? (const __nv_bfloat16*)g_w2l + layer * 32768
                    : (const __nv_bfloat16*)g_linl;

    // loader mappings
    int arow = tid >> 1, akb = (tid & 1) * 16;       // A: 4 float4 @ k=akb+q*4
    int br = tid >> 4, bc = (tid & 15) * 8;          // B: rows br, br+16; 8 bf16 cols @ bc

    int wid = tid >> 5, wm = wid >> 2, wn = wid & 3;

    wmma::fragment<wmma::accumulator, 16, 16, 16, float> acc[4][2];
#pragma unroll
    for (int i = 0; i < 4; i++)
#pragma unroll
        for (int j = 0; j < 2; j++) wmma::fill_fragment(acc[i][j], 0.f);

    float4 pa[4];
    uint4 pbh[2], pbl[2];

    auto stage_store = [&](int st) {
#pragma unroll
        for (int q = 0; q < 4; q++) {
            uint2 hi, lo;
            cvt_split4(pa[q], hi, lo);
            int off = (arow * 40 + akb + q * 4) * 2;
            *(uint2*)(sm + AHo + st * ASTG + off) = hi;
            *(uint2*)(sm + ALo + st * ASTG + off) = lo;
        }
#pragma unroll
        for (int p = 0; p < 2; p++) {
            int off = ((br + p * 16) * 136 + bc) * 2;
            *(uint4*)(sm + BHo + st * BSTG + off) = pbh[p];
            *(uint4*)(sm + BLo + st * BSTG + off) = pbl[p];
        }
    };
    auto prefetch = [&](int ch) {
#pragma unroll
        for (int q = 0; q < 4; q++)
            pa[q] = loadA<KD, MODE>(row0 + arow, ch * 32 + akb + q * 4, epsv);
#pragma unroll
        for (int p = 0; p < 2; p++) {
            int gi = ((ch * 32 + br + p * 16) * NC + n0 + bc) >> 3;
            pbh[p] = ((const uint4*)WH)[gi];
            pbl[p] = ((const uint4*)WL)[gi];
        }
    };

    prefetch(0);
    stage_store(0);
    __syncthreads();

    for (int ch = 0; ch < NCH; ch++) {
        int st = ch & 1;
        if (ch + 1 < NCH) prefetch(ch + 1);

        const __nv_bfloat16* Ah = (const __nv_bfloat16*)(sm + AHo + st * ASTG);
        const __nv_bfloat16* Al = (const __nv_bfloat16*)(sm + ALo + st * ASTG);
        const __nv_bfloat16* Bh = (const __nv_bfloat16*)(sm + BHo + st * BSTG);
        const __nv_bfloat16* Bl = (const __nv_bfloat16*)(sm + BLo + st * BSTG);

#pragma unroll
        for (int kk = 0; kk < 32; kk += 16) {
            wmma::fragment<wmma::matrix_b, 16, 16, 16, __nv_bfloat16, wmma::row_major> bh[2], bl[2];
#pragma unroll
            for (int j = 0; j < 2; j++) {
                wmma::load_matrix_sync(bh[j], Bh + kk * 136 + wn * 32 + j * 16, 136);
                wmma::load_matrix_sync(bl[j], Bl + kk * 136 + wn * 32 + j * 16, 136);
            }
            wmma::fragment<wmma::matrix_a, 16, 16, 16, __nv_bfloat16, wmma::row_major> af[4];
#pragma unroll
            for (int i = 0; i < 4; i++)
                wmma::load_matrix_sync(af[i], Ah + (wm * 64 + i * 16) * 40 + kk, 40);
#pragma unroll
            for (int i = 0; i < 4; i++)
#pragma unroll
                for (int j = 0; j < 2; j++) wmma::mma_sync(acc[i][j], af[i], bh[j], acc[i][j]);
#pragma unroll
            for (int i = 0; i < 4; i++)
#pragma unroll
                for (int j = 0; j < 2; j++) wmma::mma_sync(acc[i][j], af[i], bl[j], acc[i][j]);
#pragma unroll
            for (int i = 0; i < 4; i++)
                wmma::load_matrix_sync(af[i], Al + (wm * 64 + i * 16) * 40 + kk, 40);
#pragma unroll
            for (int i = 0; i < 4; i++)
#pragma unroll
                for (int j = 0; j < 2; j++) wmma::mma_sync(acc[i][j], af[i], bh[j], acc[i][j]);
        }
        if (ch + 1 < NCH) {
            stage_store(st ^ 1);
            __syncthreads();
        }
    }

    // epilogue: warp-tile rows are 64-aligned; NN % 64 == 0 so guard is all-or-none
    int mrow = row0 + wm * 64;
    if (mrow < NN) {
#pragma unroll
        for (int i = 0; i < 4; i++) {
            int r = mrow + i * 16;
            float* dst;
            if (MODE == 0)      dst = g_t + (size_t)r * 256 + n0;
            else if (MODE == 1) dst = g_z2 + (size_t)r * 128;
            else                dst = outP + (size_t)r * 256 + n0;
#pragma unroll
            for (int j = 0; j < 2; j++)
                wmma::store_matrix_sync(dst + wn * 32 + j * 16, acc[i][j], NC, wmma::mem_row_major);
        }
    }
}

// ---------------------------------------------------------------------------
extern "C" void kernel_launch(void* const* d_in, const int* in_sizes, int n_in,
                              void* d_out, int out_size) {
    const int*   x    = (const int*)d_in[0];
    const int*   ei   = (const int*)d_in[1];
    const int*   ea   = (const int*)d_in[2];
    const float* aemb = (const float*)d_in[3];
    const float* bemb = (const float*)d_in[4];
    const float* eps  = (const float*)d_in[5];
    const float* w1   = (const float*)d_in[6];
    const float* bn1g = (const float*)d_in[8];
    const float* bn1b = (const float*)d_in[9];
    const float* w2   = (const float*)d_in[10];
    const float* bng  = (const float*)d_in[12];
    const float* bnb  = (const float*)d_in[13];
    const float* linw = (const float*)d_in[14];
    const float* linb = (const float*)d_in[15];

    cudaFuncSetAttribute(mma_gemm<128, 0>, cudaFuncAttributeMaxDynamicSharedMemorySize, GEMM_SMEM_BYTES);
    cudaFuncSetAttribute(mma_gemm<256, 1>, cudaFuncAttributeMaxDynamicSharedMemorySize, GEMM_SMEM_BYTES);
    cudaFuncSetAttribute(mma_gemm<128, 2>, cudaFuncAttributeMaxDynamicSharedMemorySize, GEMM_SMEM_BYTES);

    convert_kernel<<<640, 256>>>(w1, w2, linw);
    atom_kernel<<<5000, 256>>>(x, aemb);
    for (int l = 0; l < 5; l++) {
        zero_kernel<<<5000, 256>>>();
        edge_kernel<<<5000, 256>>>(ei, ea, bemb + l * 3 * 16 * 128);
        mma_gemm<128, 0><<<dim3(313, 2), 256, GEMM_SMEM_BYTES>>>(l, nullptr, eps);
        stats_kernel<256><<<313, 256>>>();
        finalize_bn<<<1, 256>>>(bn1g + l * 256, bn1b + l * 256, 0, 256);
        mma_gemm<256, 1><<<dim3(313, 1), 256, GEMM_SMEM_BYTES>>>(l, nullptr, nullptr);
        stats_kernel<128><<<313, 128>>>();
        finalize_bn<<<1, 128>>>(bng + l * 128, bnb + l * 128, 1, 128);
        bn_apply_kernel<<<5000, 256>>>(l < 4 ? 1 : 0);
    }
    mma_gemm<128, 2><<<dim3(313, 2), 256, GEMM_SMEM_BYTES>>>(0, (float*)d_out, nullptr);
    bias_out_kernel<<<10000, 256>>>((float*)d_out, linb);
}

// round 13
// speedup vs baseline: 1.4019x; 1.0005x over previous
#include <cuda_runtime.h>
#include <cuda_bf16.h>
#include <mma.h>
#include <cstdint>

using namespace nvcuda;

#define NN 40000
#define NE 640000

// ------------------------- scratch (device globals) -------------------------
__device__ float g_h[NN * 128];
__device__ float g_agg[NN * 128];
__device__ float g_t[NN * 256];
__device__ float g_z2[NN * 128];
__device__ float g_stats1[512];
__device__ float g_stats2[256];
__device__ float g_bn1A[256], g_bn1B[256];
__device__ float g_bn2A[128], g_bn2B[128];
// bf16 hi/lo weights, natural [k][n] layout (row-major matrix_b)
__device__ uint4 g_w1h[5 * 128 * 256 / 8], g_w1l[5 * 128 * 256 / 8];
__device__ uint4 g_w2h[5 * 256 * 128 / 8], g_w2l[5 * 256 * 128 / 8];
__device__ uint4 g_linh[128 * 256 / 8],    g_linl[128 * 256 / 8];

// ------------------------------ small kernels ------------------------------
__global__ void zero_kernel() {
    int idx = blockIdx.x * 256 + threadIdx.x;
    ((float4*)g_agg)[idx] = make_float4(0.f, 0.f, 0.f, 0.f);
    if (blockIdx.x == 0) {
        if (threadIdx.x < 128)
            ((float4*)g_stats1)[threadIdx.x] = make_float4(0.f, 0.f, 0.f, 0.f);
        else if (threadIdx.x < 192)
            ((float4*)g_stats2)[threadIdx.x - 128] = make_float4(0.f, 0.f, 0.f, 0.f);
    }
}

__global__ void atom_kernel(const int* __restrict__ x, const float* __restrict__ aemb) {
    int gwarp = (blockIdx.x * 256 + threadIdx.x) >> 5;
    int lane = threadIdx.x & 31;
    if (gwarp >= NN) return;
    const float4* ae = (const float4*)aemb;
    float4 acc = make_float4(0.f, 0.f, 0.f, 0.f);
#pragma unroll
    for (int f = 0; f < 9; f++) {
        int idx = __ldg(x + gwarp * 9 + f);
        float4 v = ae[(f * 128 + idx) * 32 + lane];
        acc.x += v.x; acc.y += v.y; acc.z += v.z; acc.w += v.w;
    }
    ((float4*)g_h)[gwarp * 32 + lane] = acc;
}

__global__ void edge_kernel(const int* __restrict__ ei, const int* __restrict__ ea,
                            const float* __restrict__ bond) {
    __shared__ float4 bs[1536];
    for (int i = threadIdx.x; i < 1536; i += 256) bs[i] = ((const float4*)bond)[i];
    __syncthreads();
    int lane = threadIdx.x & 31;
    int warp = threadIdx.x >> 5;
    int e0 = blockIdx.x * 128 + warp * 16;
    const float4* h4 = (const float4*)g_h;
#pragma unroll 4
    for (int j = 0; j < 16; j++) {
        int e = e0 + j;
        int src = __ldg(ei + e);
        int dst = __ldg(ei + NE + e);
        int a0 = __ldg(ea + 3 * e);
        int a1 = __ldg(ea + 3 * e + 1);
        int a2 = __ldg(ea + 3 * e + 2);
        float4 v = h4[src * 32 + lane];
        float4 e0v = bs[a0 * 32 + lane];
        float4 e1v = bs[(16 + a1) * 32 + lane];
        float4 e2v = bs[(32 + a2) * 32 + lane];
        float m0 = fmaxf(v.x + e0v.x + e1v.x + e2v.x, 0.f);
        float m1 = fmaxf(v.y + e0v.y + e1v.y + e2v.y, 0.f);
        float m2 = fmaxf(v.z + e0v.z + e1v.z + e2v.z, 0.f);
        float m3 = fmaxf(v.w + e0v.w + e1v.w + e2v.w, 0.f);
        float* addr = g_agg + dst * 128 + lane * 4;
        asm volatile("red.global.add.v4.f32 [%0], {%1,%2,%3,%4};"
                     :: "l"(addr), "f"(m0), "f"(m1), "f"(m2), "f"(m3) : "memory");
    }
}

// Pre-convert all weights to bf16 hi/lo (keep [k][n] layout).
__global__ void convert_kernel(const float* __restrict__ w1, const float* __restrict__ w2,
                               const float* __restrict__ lin) {
    int idx = blockIdx.x * 256 + threadIdx.x;
    if (idx < 5 * 128 * 256) {
        float v = w1[idx];
        __nv_bfloat16 h = __float2bfloat16_rn(v);
        ((__nv_bfloat16*)g_w1h)[idx] = h;
        ((__nv_bfloat16*)g_w1l)[idx] = __float2bfloat16_rn(v - __bfloat162float(h));
        v = w2[idx];
        h = __float2bfloat16_rn(v);
        ((__nv_bfloat16*)g_w2h)[idx] = h;
        ((__nv_bfloat16*)g_w2l)[idx] = __float2bfloat16_rn(v - __bfloat162float(h));
    }
    if (idx < 128 * 256) {
        float v = lin[idx];
        __nv_bfloat16 h = __float2bfloat16_rn(v);
        ((__nv_bfloat16*)g_linh)[idx] = h;
        ((__nv_bfloat16*)g_linl)[idx] = __float2bfloat16_rn(v - __bfloat162float(h));
    }
}

// Column sums / sumsq. NC=256: g_t -> g_stats1. NC=128: g_z2 -> g_stats2.
template <int NC>
__global__ void stats_kernel() {
    const float* src = (NC == 256) ? g_t : g_z2;
    float* st = (NC == 256) ? g_stats1 : g_stats2;
    int col = threadIdx.x;
    int r0 = blockIdx.x * 128;
    int rend = min(r0 + 128, NN);
    float s = 0.f, q = 0.f;
    for (int r = r0; r < rend; r++) {
        float v = src[(size_t)r * NC + col];
        s += v;
        q = fmaf(v, v, q);
    }
    atomicAdd(&st[col], s);
    atomicAdd(&st[NC + col], q);
}

__global__ void finalize_bn(const float* __restrict__ gamma, const float* __restrict__ beta,
                            int which, int nc) {
    int c = threadIdx.x;
    if (c >= nc) return;
    const float* ST = (which == 0) ? g_stats1 : g_stats2;
    float mu = ST[c] * (1.f / NN);
    float var = ST[nc + c] * (1.f / NN) - mu * mu;
    float inv = rsqrtf(var + 1e-5f);
    float sc = gamma[c] * inv;
    float sh = beta[c] - mu * sc;
    if (which == 0) { g_bn1A[c] = sc; g_bn1B[c] = sh; }
    else            { g_bn2A[c] = sc; g_bn2B[c] = sh; }
}

__global__ void bn_apply_kernel(int do_relu) {
    int idx = blockIdx.x * 256 + threadIdx.x;
    float4 v = ((const float4*)g_z2)[idx];
    int c = (idx & 31) * 4;
    v.x = fmaf(g_bn2A[c + 0], v.x, g_bn2B[c + 0]);
    v.y = fmaf(g_bn2A[c + 1], v.y, g_bn2B[c + 1]);
    v.z = fmaf(g_bn2A[c + 2], v.z, g_bn2B[c + 2]);
    v.w = fmaf(g_bn2A[c + 3], v.w, g_bn2B[c + 3]);
    if (do_relu) {
        v.x = fmaxf(v.x, 0.f); v.y = fmaxf(v.y, 0.f);
        v.z = fmaxf(v.z, 0.f); v.w = fmaxf(v.w, 0.f);
    }
    ((float4*)g_h)[idx] = v;
}

__global__ void bias_out_kernel(float* __restrict__ out, const float* __restrict__ linb) {
    int idx = blockIdx.x * 256 + threadIdx.x;  // float4 over NN*256/4
    float4 v = ((float4*)out)[idx];
    int c = (idx & 63) * 4;
    v.x += __ldg(linb + c + 0);
    v.y += __ldg(linb + c + 1);
    v.z += __ldg(linb + c + 2);
    v.w += __ldg(linb + c + 3);
    ((float4*)out)[idx] = v;
}

// ----------------------- bf16x3 WMMA GEMM (tensor pipe) ---------------------
// 128x128 tile/CTA, BK=32 double-buffered. 8 warps, warp tile 64x32.
// MODE 0: A=(1+eps)*h+agg, B=w1  -> g_t    (bias dropped: BN-invariant)
// MODE 1: A=relu(bn1(g_t)), B=w2 -> g_z2   (bias dropped: BN-invariant)
// MODE 2: A=h,              B=lin -> out   (lin_b added by bias_out_kernel)
template <int KD, int MODE>
__device__ __forceinline__ float4 loadA(int grow, int k, float epsv) {
    float4 v = make_float4(0.f, 0.f, 0.f, 0.f);
    if (grow < NN) {
        int gi = (grow * KD + k) >> 2;
        if (MODE == 0) {
            float4 a = ((const float4*)g_h)[gi];
            float4 b = ((const float4*)g_agg)[gi];
            v.x = fmaf(epsv, a.x, b.x);
            v.y = fmaf(epsv, a.y, b.y);
            v.z = fmaf(epsv, a.z, b.z);
            v.w = fmaf(epsv, a.w, b.w);
        } else if (MODE == 1) {
            float4 a = ((const float4*)g_t)[gi];
            v.x = fmaxf(fmaf(g_bn1A[k + 0], a.x, g_bn1B[k + 0]), 0.f);
            v.y = fmaxf(fmaf(g_bn1A[k + 1], a.y, g_bn1B[k + 1]), 0.f);
            v.z = fmaxf(fmaf(g_bn1A[k + 2], a.z, g_bn1B[k + 2]), 0.f);
            v.w = fmaxf(fmaf(g_bn1A[k + 3], a.w, g_bn1B[k + 3]), 0.f);
        } else {
            v = ((const float4*)g_h)[gi];
        }
    }
    return v;
}

__device__ __forceinline__ void cvt_split4(float4 v, uint2& hi, uint2& lo) {
    __nv_bfloat16 hx = __float2bfloat16_rn(v.x), hy = __float2bfloat16_rn(v.y);
    __nv_bfloat16 hz = __float2bfloat16_rn(v.z), hw = __float2bfloat16_rn(v.w);
    __nv_bfloat162 h01, h23, l01, l23;
    h01.x = hx; h01.y = hy; h23.x = hz; h23.y = hw;
    l01.x = __float2bfloat16_rn(v.x - __bfloat162float(hx));
    l01.y = __float2bfloat16_rn(v.y - __bfloat162float(hy));
    l23.x = __float2bfloat16_rn(v.z - __bfloat162float(hz));
    l23.y = __float2bfloat16_rn(v.w - __bfloat162float(hw));
    hi.x = *(uint32_t*)&h01; hi.y = *(uint32_t*)&h23;
    lo.x = *(uint32_t*)&l01; lo.y = *(uint32_t*)&l23;
}

// smem layout (bytes): Ahi[2][128][40] | Alo[2][128][40] | Bhi[2][32][136] | Blo[2][32][136]
#define AHo 0
#define ALo 20480
#define BHo 40960
#define BLo 58368
#define ASTG 10240
#define BSTG 8704
#define GEMM_SMEM_BYTES 75776

template <int KD, int MODE>
__global__ void __launch_bounds__(256)
mma_gemm(int layer, float* __restrict__ outP, const float* __restrict__ epsp) {
    extern __shared__ char sm[];
    constexpr int NC = (MODE == 1) ? 128 : 256;
    constexpr int NCH = KD / 32;

    int tid = threadIdx.x;
    int row0 = blockIdx.x * 128;
    int n0 = blockIdx.y * 128;

    float epsv = (MODE == 0) ? 1.f + __ldg(epsp + layer) : 0.f;
    const __nv_bfloat16* WH =
        (MODE == 0) ? (const __nv_bfloat16*)g_w1h + layer * 32768
      : (MODE == 1) ? (const __nv_bfloat16*)g_w2h + layer * 32768
                    : (const __nv_bfloat16*)g_linh;
    const __nv_bfloat16* WL =
        (MODE == 0) ? (const __nv_bfloat16*)g_w1l + layer * 32768
      : (MODE == 1) ? (const __nv_bfloat16*)g_w2l + layer * 32768
                    : (const __nv_bfloat16*)g_linl;

    // loader mappings
    int arow = tid >> 1, akb = (tid & 1) * 16;       // A: 4 float4 @ k=akb+q*4
    int br = tid >> 4, bc = (tid & 15) * 8;          // B: rows br, br+16; 8 bf16 cols @ bc

    int wid = tid >> 5, wm = wid >> 2, wn = wid & 3;

    wmma::fragment<wmma::accumulator, 16, 16, 16, float> acc[4][2];
#pragma unroll
    for (int i = 0; i < 4; i++)
#pragma unroll
        for (int j = 0; j < 2; j++) wmma::fill_fragment(acc[i][j], 0.f);

    float4 pa[4];
    uint4 pbh[2], pbl[2];

    auto stage_store = [&](int st) {
#pragma unroll
        for (int q = 0; q < 4; q++) {
            uint2 hi, lo;
            cvt_split4(pa[q], hi, lo);
            int off = (arow * 40 + akb + q * 4) * 2;
            *(uint2*)(sm + AHo + st * ASTG + off) = hi;
            *(uint2*)(sm + ALo + st * ASTG + off) = lo;
        }
#pragma unroll
        for (int p = 0; p < 2; p++) {
            int off = ((br + p * 16) * 136 + bc) * 2;
            *(uint4*)(sm + BHo + st * BSTG + off) = pbh[p];
            *(uint4*)(sm + BLo + st * BSTG + off) = pbl[p];
        }
    };
    auto prefetch = [&](int ch) {
#pragma unroll
        for (int q = 0; q < 4; q++)
            pa[q] = loadA<KD, MODE>(row0 + arow, ch * 32 + akb + q * 4, epsv);
#pragma unroll
        for (int p = 0; p < 2; p++) {
            int gi = ((ch * 32 + br + p * 16) * NC + n0 + bc) >> 3;
            pbh[p] = ((const uint4*)WH)[gi];
            pbl[p] = ((const uint4*)WL)[gi];
        }
    };

    prefetch(0);
    stage_store(0);
    __syncthreads();

    for (int ch = 0; ch < NCH; ch++) {
        int st = ch & 1;
        if (ch + 1 < NCH) prefetch(ch + 1);

        const __nv_bfloat16* Ah = (const __nv_bfloat16*)(sm + AHo + st * ASTG);
        const __nv_bfloat16* Al = (const __nv_bfloat16*)(sm + ALo + st * ASTG);
        const __nv_bfloat16* Bh = (const __nv_bfloat16*)(sm + BHo + st * BSTG);
        const __nv_bfloat16* Bl = (const __nv_bfloat16*)(sm + BLo + st * BSTG);

#pragma unroll
        for (int kk = 0; kk < 32; kk += 16) {
            wmma::fragment<wmma::matrix_b, 16, 16, 16, __nv_bfloat16, wmma::row_major> bh[2], bl[2];
#pragma unroll
            for (int j = 0; j < 2; j++) {
                wmma::load_matrix_sync(bh[j], Bh + kk * 136 + wn * 32 + j * 16, 136);
                wmma::load_matrix_sync(bl[j], Bl + kk * 136 + wn * 32 + j * 16, 136);
            }
            wmma::fragment<wmma::matrix_a, 16, 16, 16, __nv_bfloat16, wmma::row_major> af[4];
#pragma unroll
            for (int i = 0; i < 4; i++)
                wmma::load_matrix_sync(af[i], Ah + (wm * 64 + i * 16) * 40 + kk, 40);
#pragma unroll
            for (int i = 0; i < 4; i++)
#pragma unroll
                for (int j = 0; j < 2; j++) wmma::mma_sync(acc[i][j], af[i], bh[j], acc[i][j]);
#pragma unroll
            for (int i = 0; i < 4; i++)
#pragma unroll
                for (int j = 0; j < 2; j++) wmma::mma_sync(acc[i][j], af[i], bl[j], acc[i][j]);
#pragma unroll
            for (int i = 0; i < 4; i++)
                wmma::load_matrix_sync(af[i], Al + (wm * 64 + i * 16) * 40 + kk, 40);
#pragma unroll
            for (int i = 0; i < 4; i++)
#pragma unroll
                for (int j = 0; j < 2; j++) wmma::mma_sync(acc[i][j], af[i], bh[j], acc[i][j]);
        }
        if (ch + 1 < NCH) {
            stage_store(st ^ 1);
            __syncthreads();
        }
    }

    // epilogue: warp-tile rows are 64-aligned; NN % 64 == 0 so guard is all-or-none
    int mrow = row0 + wm * 64;
    if (mrow < NN) {
#pragma unroll
        for (int i = 0; i < 4; i++) {
            int r = mrow + i * 16;
            float* dst;
            if (MODE == 0)      dst = g_t + (size_t)r * 256 + n0;
            else if (MODE == 1) dst = g_z2 + (size_t)r * 128;
            else                dst = outP + (size_t)r * 256 + n0;
#pragma unroll
            for (int j = 0; j < 2; j++)
                wmma::store_matrix_sync(dst + wn * 32 + j * 16, acc[i][j], NC, wmma::mem_row_major);
        }
    }
}

// ---------------------------------------------------------------------------
extern "C" void kernel_launch(void* const* d_in, const int* in_sizes, int n_in,
                              void* d_out, int out_size) {
    const int*   x    = (const int*)d_in[0];
    const int*   ei   = (const int*)d_in[1];
    const int*   ea   = (const int*)d_in[2];
    const float* aemb = (const float*)d_in[3];
    const float* bemb = (const float*)d_in[4];
    const float* eps  = (const float*)d_in[5];
    const float* w1   = (const float*)d_in[6];
    const float* bn1g = (const float*)d_in[8];
    const float* bn1b = (const float*)d_in[9];
    const float* w2   = (const float*)d_in[10];
    const float* bng  = (const float*)d_in[12];
    const float* bnb  = (const float*)d_in[13];
    const float* linw = (const float*)d_in[14];
    const float* linb = (const float*)d_in[15];

    cudaFuncSetAttribute(mma_gemm<128, 0>, cudaFuncAttributeMaxDynamicSharedMemorySize, GEMM_SMEM_BYTES);
    cudaFuncSetAttribute(mma_gemm<256, 1>, cudaFuncAttributeMaxDynamicSharedMemorySize, GEMM_SMEM_BYTES);
    cudaFuncSetAttribute(mma_gemm<128, 2>, cudaFuncAttributeMaxDynamicSharedMemorySize, GEMM_SMEM_BYTES);

    convert_kernel<<<640, 256>>>(w1, w2, linw);
    atom_kernel<<<5000, 256>>>(x, aemb);
    for (int l = 0; l < 5; l++) {
        zero_kernel<<<5000, 256>>>();
        edge_kernel<<<5000, 256>>>(ei, ea, bemb + l * 3 * 16 * 128);
        mma_gemm<128, 0><<<dim3(313, 2), 256, GEMM_SMEM_BYTES>>>(l, nullptr, eps);
        stats_kernel<256><<<313, 256>>>();
        finalize_bn<<<1, 256>>>(bn1g + l * 256, bn1b + l * 256, 0, 256);
        mma_gemm<256, 1><<<dim3(313, 1), 256, GEMM_SMEM_BYTES>>>(l, nullptr, nullptr);
        stats_kernel<128><<<313, 128>>>();
        finalize_bn<<<1, 128>>>(bng + l * 128, bnb + l * 128, 1, 128);
        bn_apply_kernel<<<5000, 256>>>(l < 4 ? 1 : 0);
    }
    mma_gemm<128, 2><<<dim3(313, 2), 256, GEMM_SMEM_BYTES>>>(0, (float*)d_out, nullptr);
    bias_out_kernel<<<10000, 256>>>((float*)d_out, linb);
}

// round 15
// speedup vs baseline: 1.4267x; 1.0177x over previous
#include <cuda_runtime.h>
#include <cuda_bf16.h>
#include <mma.h>
#include <cstdint>

using namespace nvcuda;

#define NN 40000
#define NE 640000

// ------------------------- scratch (device globals) -------------------------
__device__ float g_h[NN * 128];
__device__ float g_agg[NN * 128];
__device__ float g_t[NN * 256];
__device__ float g_z2[NN * 128];
__device__ float g_stats1[512];
__device__ float g_stats2[256];
__device__ float g_bn1A[256], g_bn1B[256];
__device__ float g_bn2A[128], g_bn2B[128];
__device__ unsigned g_cnt[2];
__device__ float g_bias_tile[16 * 256];  // 16 identical rows of lin_b
// bf16 hi/lo weights, natural [k][n] layout (row-major matrix_b)
__device__ uint4 g_w1h[5 * 128 * 256 / 8], g_w1l[5 * 128 * 256 / 8];
__device__ uint4 g_w2h[5 * 256 * 128 / 8], g_w2l[5 * 256 * 128 / 8];
__device__ uint4 g_linh[128 * 256 / 8],    g_linl[128 * 256 / 8];

// ------------------------------ PTX helpers --------------------------------
__device__ __forceinline__ uint32_t s2u(const void* p) {
    uint32_t a;
    asm("{ .reg .u64 t; cvta.to.shared.u64 t, %1; cvt.u32.u64 %0, t; }" : "=r"(a) : "l"(p));
    return a;
}
__device__ __forceinline__ void cp16(void* smem_dst, const void* gsrc) {
    asm volatile("cp.async.cg.shared.global [%0], [%1], 16;"
                 :: "r"(s2u(smem_dst)), "l"(gsrc) : "memory");
}
__device__ __forceinline__ void cp_commit() {
    asm volatile("cp.async.commit_group;" ::: "memory");
}
__device__ __forceinline__ void cp_wait0() {
    asm volatile("cp.async.wait_group 0;" ::: "memory");
}

// ------------------------------ small kernels ------------------------------
__global__ void atom_kernel(const int* __restrict__ x, const float* __restrict__ aemb) {
    int gwarp = (blockIdx.x * 256 + threadIdx.x) >> 5;
    int lane = threadIdx.x & 31;
    if (gwarp >= NN) return;
    const float4* ae = (const float4*)aemb;
    float4 acc = make_float4(0.f, 0.f, 0.f, 0.f);
#pragma unroll
    for (int f = 0; f < 9; f++) {
        int idx = __ldg(x + gwarp * 9 + f);
        float4 v = ae[(f * 128 + idx) * 32 + lane];
        acc.x += v.x; acc.y += v.y; acc.z += v.z; acc.w += v.w;
    }
    ((float4*)g_h)[gwarp * 32 + lane] = acc;
    ((float4*)g_agg)[gwarp * 32 + lane] = make_float4(0.f, 0.f, 0.f, 0.f);  // fused zero
}

__global__ void edge_kernel(const int* __restrict__ ei, const int* __restrict__ ea,
                            const float* __restrict__ bond) {
    __shared__ float4 bs[1536];
    for (int i = threadIdx.x; i < 1536; i += 256) bs[i] = ((const float4*)bond)[i];
    __syncthreads();
    int lane = threadIdx.x & 31;
    int warp = threadIdx.x >> 5;
    int e0 = blockIdx.x * 128 + warp * 16;
    const float4* h4 = (const float4*)g_h;
#pragma unroll 4
    for (int j = 0; j < 16; j++) {
        int e = e0 + j;
        int src = __ldg(ei + e);
        int dst = __ldg(ei + NE + e);
        int a0 = __ldg(ea + 3 * e);
        int a1 = __ldg(ea + 3 * e + 1);
        int a2 = __ldg(ea + 3 * e + 2);
        float4 v = h4[src * 32 + lane];
        float4 e0v = bs[a0 * 32 + lane];
        float4 e1v = bs[(16 + a1) * 32 + lane];
        float4 e2v = bs[(32 + a2) * 32 + lane];
        float m0 = fmaxf(v.x + e0v.x + e1v.x + e2v.x, 0.f);
        float m1 = fmaxf(v.y + e0v.y + e1v.y + e2v.y, 0.f);
        float m2 = fmaxf(v.z + e0v.z + e1v.z + e2v.z, 0.f);
        float m3 = fmaxf(v.w + e0v.w + e1v.w + e2v.w, 0.f);
        float* addr = g_agg + dst * 128 + lane * 4;
        asm volatile("red.global.add.v4.f32 [%0], {%1,%2,%3,%4};"
                     :: "l"(addr), "f"(m0), "f"(m1), "f"(m2), "f"(m3) : "memory");
    }
}

// Pre-convert weights to bf16 hi/lo; zero stats/counters; build bias tile.
__global__ void convert_kernel(const float* __restrict__ w1, const float* __restrict__ w2,
                               const float* __restrict__ lin, const float* __restrict__ linb) {
    int idx = blockIdx.x * 256 + threadIdx.x;
    if (idx < 5 * 128 * 256) {
        float v = w1[idx];
        __nv_bfloat16 h = __float2bfloat16_rn(v);
        ((__nv_bfloat16*)g_w1h)[idx] = h;
        ((__nv_bfloat16*)g_w1l)[idx] = __float2bfloat16_rn(v - __bfloat162float(h));
        v = w2[idx];
        h = __float2bfloat16_rn(v);
        ((__nv_bfloat16*)g_w2h)[idx] = h;
        ((__nv_bfloat16*)g_w2l)[idx] = __float2bfloat16_rn(v - __bfloat162float(h));
    }
    if (idx < 128 * 256) {
        float v = lin[idx];
        __nv_bfloat16 h = __float2bfloat16_rn(v);
        ((__nv_bfloat16*)g_linh)[idx] = h;
        ((__nv_bfloat16*)g_linl)[idx] = __float2bfloat16_rn(v - __bfloat162float(h));
    }
    if (idx < 16 * 256) g_bias_tile[idx] = __ldg(linb + (idx & 255));
    if (idx < 512) g_stats1[idx] = 0.f;
    if (idx < 256) g_stats2[idx] = 0.f;
    if (idx < 2) g_cnt[idx] = 0u;
}

// Column stats + fused BN finalize (last-block-done). Self-resets stats & cnt.
template <int NC, int WHICH>
__global__ void stats_kernel(const float* __restrict__ gamma, const float* __restrict__ beta) {
    const float* src = (NC == 256) ? g_t : g_z2;
    float* st = (NC == 256) ? g_stats1 : g_stats2;
    int col = threadIdx.x;
    int r0 = blockIdx.x * 128;
    int rend = min(r0 + 128, NN);
    float s = 0.f, q = 0.f;
    for (int r = r0; r < rend; r++) {
        float v = src[(size_t)r * NC + col];
        s += v;
        q = fmaf(v, v, q);
    }
    atomicAdd(&st[col], s);
    atomicAdd(&st[NC + col], q);
    __threadfence();
    __shared__ unsigned done;
    if (threadIdx.x == 0) done = atomicAdd(&g_cnt[WHICH], 1u);
    __syncthreads();
    if (done == gridDim.x - 1) {
        float mu = st[col] * (1.f / NN);
        float var = st[NC + col] * (1.f / NN) - mu * mu;
        float sc = gamma[col] * rsqrtf(var + 1e-5f);
        float sh = beta[col] - mu * sc;
        if (NC == 256) { g_bn1A[col] = sc; g_bn1B[col] = sh; }
        else           { g_bn2A[col] = sc; g_bn2B[col] = sh; }
        st[col] = 0.f;
        st[NC + col] = 0.f;
        if (col == 0) g_cnt[WHICH] = 0u;
    }
}

// Apply BN2 (+relu) h = act(bn2(z2)); also re-zeroes g_agg for next layer.
__global__ void bn_apply_kernel(int do_relu) {
    int idx = blockIdx.x * 256 + threadIdx.x;
    float4 v = ((const float4*)g_z2)[idx];
    int c = (idx & 31) * 4;
    v.x = fmaf(g_bn2A[c + 0], v.x, g_bn2B[c + 0]);
    v.y = fmaf(g_bn2A[c + 1], v.y, g_bn2B[c + 1]);
    v.z = fmaf(g_bn2A[c + 2], v.z, g_bn2B[c + 2]);
    v.w = fmaf(g_bn2A[c + 3], v.w, g_bn2B[c + 3]);
    if (do_relu) {
        v.x = fmaxf(v.x, 0.f); v.y = fmaxf(v.y, 0.f);
        v.z = fmaxf(v.z, 0.f); v.w = fmaxf(v.w, 0.f);
    }
    ((float4*)g_h)[idx] = v;
    ((float4*)g_agg)[idx] = make_float4(0.f, 0.f, 0.f, 0.f);  // fused zero
}

// ----------------------- bf16x3 WMMA GEMM (tensor pipe) ---------------------
// CTA tile 128xNC, warp tile 64x64. NC=256: 8 warps (2x4). NC=128: 4 warps (2x2).
// BK=32 double-buffered; B via cp.async; A fused-converted to bf16 hi/lo.
// MODE 0: A=(1+eps)*h+agg, B=w1  -> g_t
// MODE 1: A=relu(bn1(g_t)), B=w2 -> g_z2
// MODE 2: A=h, B=lin, acc preloaded with lin_b broadcast tile -> out
template <int KD, int MODE>
__device__ __forceinline__ float4 loadA(int grow, int k, float epsv) {
    float4 v = make_float4(0.f, 0.f, 0.f, 0.f);
    if (grow < NN) {
        int gi = (grow * KD + k) >> 2;
        if (MODE == 0) {
            float4 a = ((const float4*)g_h)[gi];
            float4 b = ((const float4*)g_agg)[gi];
            v.x = fmaf(epsv, a.x, b.x);
            v.y = fmaf(epsv, a.y, b.y);
            v.z = fmaf(epsv, a.z, b.z);
            v.w = fmaf(epsv, a.w, b.w);
        } else if (MODE == 1) {
            float4 a = ((const float4*)g_t)[gi];
            v.x = fmaxf(fmaf(g_bn1A[k + 0], a.x, g_bn1B[k + 0]), 0.f);
            v.y = fmaxf(fmaf(g_bn1A[k + 1], a.y, g_bn1B[k + 1]), 0.f);
            v.z = fmaxf(fmaf(g_bn1A[k + 2], a.z, g_bn1B[k + 2]), 0.f);
            v.w = fmaxf(fmaf(g_bn1A[k + 3], a.w, g_bn1B[k + 3]), 0.f);
        } else {
            v = ((const float4*)g_h)[gi];
        }
    }
    return v;
}

__device__ __forceinline__ void cvt_split4(float4 v, uint2& hi, uint2& lo) {
    __nv_bfloat16 hx = __float2bfloat16_rn(v.x), hy = __float2bfloat16_rn(v.y);
    __nv_bfloat16 hz = __float2bfloat16_rn(v.z), hw = __float2bfloat16_rn(v.w);
    __nv_bfloat162 h01, h23, l01, l23;
    h01.x = hx; h01.y = hy; h23.x = hz; h23.y = hw;
    l01.x = __float2bfloat16_rn(v.x - __bfloat162float(hx));
    l01.y = __float2bfloat16_rn(v.y - __bfloat162float(hy));
    l23.x = __float2bfloat16_rn(v.z - __bfloat162float(hz));
    l23.y = __float2bfloat16_rn(v.w - __bfloat162float(hw));
    hi.x = *(uint32_t*)&h01; hi.y = *(uint32_t*)&h23;
    lo.x = *(uint32_t*)&l01; lo.y = *(uint32_t*)&l23;
}

template <int NC> constexpr int gemm_smem() {
    // A: 2 stages x (hi+lo) x 128x40 bf16 ; B: 2 stages x (hi+lo) x 32x(NC+8) bf16
    return 4 * (128 * 40 * 2) + 4 * (32 * (NC + 8) * 2);
}

template <int KD, int NC, int MODE>
__global__ void __launch_bounds__(NC == 128 ? 128 : 256)
mma_gemm(int layer, float* __restrict__ outP, const float* __restrict__ epsp) {
    extern __shared__ char sm[];
    constexpr int THREADS = (NC == 128) ? 128 : 256;
    constexpr int AQ = 1024 / THREADS;          // float4 A-loads per thread
    constexpr int BROW = NC + 8;
    constexpr int ASTG = 128 * 40 * 2;
    constexpr int BSTG = 32 * BROW * 2;
    constexpr int AH_ = 0, AL_ = 2 * ASTG, BH_ = 4 * ASTG, BL_ = 4 * ASTG + 2 * BSTG;
    constexpr int NCH = KD / 32;
    constexpr int BU = (32 * NC / 8) / THREADS;  // uint4 B-loads/thread/table (=4)
    static_assert(BU >= 1, "B loader trip count must be positive");

    int tid = threadIdx.x;
    int row0 = blockIdx.x * 128;
    int wid = tid >> 5;
    int wm = (NC == 128) ? (wid >> 1) : (wid >> 2);
    int wn = (NC == 128) ? (wid & 1) : (wid & 3);

    float epsv = (MODE == 0) ? 1.f + __ldg(epsp + layer) : 0.f;
    const uint4* WH = (MODE == 0) ? g_w1h + layer * 4096
                    : (MODE == 1) ? g_w2h + layer * 4096 : g_linh;
    const uint4* WL = (MODE == 0) ? g_w1l + layer * 4096
                    : (MODE == 1) ? g_w2l + layer * 4096 : g_linl;

    wmma::fragment<wmma::accumulator, 16, 16, 16, float> acc[4][4];
#pragma unroll
    for (int i = 0; i < 4; i++)
#pragma unroll
        for (int j = 0; j < 4; j++) {
            if (MODE == 2)
                wmma::load_matrix_sync(acc[i][j], g_bias_tile + wn * 64 + j * 16, 256,
                                       wmma::mem_row_major);
            else
                wmma::fill_fragment(acc[i][j], 0.f);
        }

    float4 pa[AQ];

    auto prefetchA = [&](int ch) {
#pragma unroll
        for (int q = 0; q < AQ; q++) {
            int fi = q * THREADS + tid;
            pa[q] = loadA<KD, MODE>(row0 + (fi >> 3), ch * 32 + (fi & 7) * 4, epsv);
        }
    };
    auto storeA = [&](int st) {
#pragma unroll
        for (int q = 0; q < AQ; q++) {
            int fi = q * THREADS + tid;
            int row = fi >> 3, k = (fi & 7) * 4;
            uint2 hi, lo;
            cvt_split4(pa[q], hi, lo);
            *(uint2*)(sm + AH_ + st * ASTG + (row * 40 + k) * 2) = hi;
            *(uint2*)(sm + AL_ + st * ASTG + (row * 40 + k) * 2) = lo;
        }
    };
    auto loadB = [&](int ch, int st) {
#pragma unroll
        for (int u = 0; u < BU; u++) {
            int ui = u * THREADS + tid;
            int row = ui / (NC / 8), cb = (ui % (NC / 8)) * 8;
            int gi = ((ch * 32 + row) * NC + cb) >> 3;
            cp16(sm + BH_ + st * BSTG + (row * BROW + cb) * 2, WH + gi);
            cp16(sm + BL_ + st * BSTG + (row * BROW + cb) * 2, WL + gi);
        }
        cp_commit();
    };

    prefetchA(0);
    loadB(0, 0);
    storeA(0);
    cp_wait0();
    __syncthreads();

    for (int ch = 0; ch < NCH; ch++) {
        int st = ch & 1;
        if (ch + 1 < NCH) {
            loadB(ch + 1, st ^ 1);
            prefetchA(ch + 1);
        }
        const __nv_bfloat16* Ah = (const __nv_bfloat16*)(sm + AH_ + st * ASTG);
        const __nv_bfloat16* Al = (const __nv_bfloat16*)(sm + AL_ + st * ASTG);
        const __nv_bfloat16* Bh = (const __nv_bfloat16*)(sm + BH_ + st * BSTG);
        const __nv_bfloat16* Bl = (const __nv_bfloat16*)(sm + BL_ + st * BSTG);

#pragma unroll
        for (int kk = 0; kk < 32; kk += 16) {
            wmma::fragment<wmma::matrix_b, 16, 16, 16, __nv_bfloat16, wmma::row_major> bh[4], bl[4];
#pragma unroll
            for (int j = 0; j < 4; j++) {
                wmma::load_matrix_sync(bh[j], Bh + kk * BROW + wn * 64 + j * 16, BROW);
                wmma::load_matrix_sync(bl[j], Bl + kk * BROW + wn * 64 + j * 16, BROW);
            }
            wmma::fragment<wmma::matrix_a, 16, 16, 16, __nv_bfloat16, wmma::row_major> af;
#pragma unroll
            for (int i = 0; i < 4; i++) {
                wmma::load_matrix_sync(af, Ah + (wm * 64 + i * 16) * 40 + kk, 40);
#pragma unroll
                for (int j = 0; j < 4; j++) wmma::mma_sync(acc[i][j], af, bh[j], acc[i][j]);
#pragma unroll
                for (int j = 0; j < 4; j++) wmma::mma_sync(acc[i][j], af, bl[j], acc[i][j]);
            }
#pragma unroll
            for (int i = 0; i < 4; i++) {
                wmma::load_matrix_sync(af, Al + (wm * 64 + i * 16) * 40 + kk, 40);
#pragma unroll
                for (int j = 0; j < 4; j++) wmma::mma_sync(acc[i][j], af, bh[j], acc[i][j]);
            }
        }
        if (ch + 1 < NCH) {
            storeA(st ^ 1);
            cp_wait0();
            __syncthreads();
        }
    }

    // epilogue: NN % 64 == 0, warp-tile rows 64-aligned -> all-or-none guard
    int mrow = row0 + wm * 64;
    if (mrow < NN) {
#pragma unroll
        for (int i = 0; i < 4; i++) {
            int r = mrow + i * 16;
            float* dst;
            if (MODE == 0)      dst = g_t + (size_t)r * 256;
            else if (MODE == 1) dst = g_z2 + (size_t)r * 128;
            else                dst = outP + (size_t)r * 256;
#pragma unroll
            for (int j = 0; j < 4; j++)
                wmma::store_matrix_sync(dst + wn * 64 + j * 16, acc[i][j], NC,
                                        wmma::mem_row_major);
        }
    }
}

// ---------------------------------------------------------------------------
extern "C" void kernel_launch(void* const* d_in, const int* in_sizes, int n_in,
                              void* d_out, int out_size) {
    const int*   x    = (const int*)d_in[0];
    const int*   ei   = (const int*)d_in[1];
    const int*   ea   = (const int*)d_in[2];
    const float* aemb = (const float*)d_in[3];
    const float* bemb = (const float*)d_in[4];
    const float* eps  = (const float*)d_in[5];
    const float* w1   = (const float*)d_in[6];
    const float* bn1g = (const float*)d_in[8];
    const float* bn1b = (const float*)d_in[9];
    const float* w2   = (const float*)d_in[10];
    const float* bng  = (const float*)d_in[12];
    const float* bnb  = (const float*)d_in[13];
    const float* linw = (const float*)d_in[14];
    const float* linb = (const float*)d_in[15];

    constexpr int S256 = gemm_smem<256>();
    constexpr int S128 = gemm_smem<128>();
    cudaFuncSetAttribute(mma_gemm<128, 256, 0>, cudaFuncAttributeMaxDynamicSharedMemorySize, S256);
    cudaFuncSetAttribute(mma_gemm<256, 128, 1>, cudaFuncAttributeMaxDynamicSharedMemorySize, S128);
    cudaFuncSetAttribute(mma_gemm<128, 256, 2>, cudaFuncAttributeMaxDynamicSharedMemorySize, S256);

    convert_kernel<<<640, 256>>>(w1, w2, linw, linb);
    atom_kernel<<<5000, 256>>>(x, aemb);
    for (int l = 0; l < 5; l++) {
        edge_kernel<<<5000, 256>>>(ei, ea, bemb + l * 3 * 16 * 128);
        mma_gemm<128, 256, 0><<<313, 256, S256>>>(l, nullptr, eps);
        stats_kernel<256, 0><<<313, 256>>>(bn1g + l * 256, bn1b + l * 256);
        mma_gemm<256, 128, 1><<<313, 128, S128>>>(l, nullptr, nullptr);
        stats_kernel<128, 1><<<313, 128>>>(bng + l * 128, bnb + l * 128);
        bn_apply_kernel<<<5000, 256>>>(l < 4 ? 1 : 0);
    }
    mma_gemm<128, 256, 2><<<313, 256, S256>>>(0, (float*)d_out, nullptr);
}

// round 16
// speedup vs baseline: 1.6816x; 1.1787x over previous
#include <cuda_runtime.h>
#include <cuda_bf16.h>
#include <mma.h>
#include <cstdint>

using namespace nvcuda;

#define NN 40000
#define NE 640000

// ------------------------- scratch (device globals) -------------------------
__device__ float g_h[NN * 128];
__device__ float g_agg[NN * 128];
__device__ float g_t[NN * 256];
__device__ float g_z2[NN * 128];
__device__ float g_stats1[512];
__device__ float g_stats2[256];
__device__ float g_bn1A[256], g_bn1B[256];
__device__ float g_bn2A[128], g_bn2B[128];
__device__ unsigned g_cnt[2];
__device__ float g_bias_tile[16 * 256];     // 16 identical rows of lin_b
__device__ int g_ecode[NE];                 // packed (a0,a1,a2) per edge
__device__ float g_bcombo[4096 * 128];      // per-layer bond-combo table
// bf16 hi/lo weights, natural [k][n] layout (row-major matrix_b)
__device__ uint4 g_w1h[5 * 128 * 256 / 8], g_w1l[5 * 128 * 256 / 8];
__device__ uint4 g_w2h[5 * 256 * 128 / 8], g_w2l[5 * 256 * 128 / 8];
__device__ uint4 g_linh[128 * 256 / 8],    g_linl[128 * 256 / 8];

// ------------------------------ PTX helpers --------------------------------
__device__ __forceinline__ uint32_t s2u(const void* p) {
    uint32_t a;
    asm("{ .reg .u64 t; cvta.to.shared.u64 t, %1; cvt.u32.u64 %0, t; }" : "=r"(a) : "l"(p));
    return a;
}
__device__ __forceinline__ void cp16(void* smem_dst, const void* gsrc) {
    asm volatile("cp.async.cg.shared.global [%0], [%1], 16;"
                 :: "r"(s2u(smem_dst)), "l"(gsrc) : "memory");
}
__device__ __forceinline__ void cp_commit() {
    asm volatile("cp.async.commit_group;" ::: "memory");
}
__device__ __forceinline__ void cp_wait0() {
    asm volatile("cp.async.wait_group 0;" ::: "memory");
}

// ------------------------------ small kernels ------------------------------
__global__ void atom_kernel(const int* __restrict__ x, const float* __restrict__ aemb) {
    int gwarp = (blockIdx.x * 256 + threadIdx.x) >> 5;
    int lane = threadIdx.x & 31;
    if (gwarp >= NN) return;
    const float4* ae = (const float4*)aemb;
    float4 acc = make_float4(0.f, 0.f, 0.f, 0.f);
#pragma unroll
    for (int f = 0; f < 9; f++) {
        int idx = __ldg(x + gwarp * 9 + f);
        float4 v = ae[(f * 128 + idx) * 32 + lane];
        acc.x += v.x; acc.y += v.y; acc.z += v.z; acc.w += v.w;
    }
    ((float4*)g_h)[gwarp * 32 + lane] = acc;
    ((float4*)g_agg)[gwarp * 32 + lane] = make_float4(0.f, 0.f, 0.f, 0.f);  // fused zero
}

// Build the 4096-combo bond table for one layer: bcombo[code] = b0[a0]+b1[a1]+b2[a2]
__global__ void bond_combo_kernel(const float* __restrict__ bond) {
    int idx = blockIdx.x * 256 + threadIdx.x;   // over 4096*32 float4
    int code = idx >> 5, c4 = idx & 31;
    int a0 = code & 15, a1 = (code >> 4) & 15, a2 = code >> 8;
    const float4* b4 = (const float4*)bond;
    float4 v0 = b4[a0 * 32 + c4];
    float4 v1 = b4[(16 + a1) * 32 + c4];
    float4 v2 = b4[(32 + a2) * 32 + c4];
    float4 o;
    o.x = v0.x + v1.x + v2.x;
    o.y = v0.y + v1.y + v2.y;
    o.z = v0.z + v1.z + v2.z;
    o.w = v0.w + v1.w + v2.w;
    ((float4*)g_bcombo)[idx] = o;
}

__global__ void edge_kernel(const int* __restrict__ ei) {
    int lane = threadIdx.x & 31;
    int warp = threadIdx.x >> 5;
    int e0 = blockIdx.x * 128 + warp * 16;
    const float4* h4 = (const float4*)g_h;
    const float4* bc4 = (const float4*)g_bcombo;
#pragma unroll 4
    for (int j = 0; j < 16; j++) {
        int e = e0 + j;
        int src = __ldg(ei + e);
        int dst = __ldg(ei + NE + e);
        int code = __ldg(g_ecode + e);
        float4 v = h4[src * 32 + lane];
        float4 bv = bc4[code * 32 + lane];
        float m0 = fmaxf(v.x + bv.x, 0.f);
        float m1 = fmaxf(v.y + bv.y, 0.f);
        float m2 = fmaxf(v.z + bv.z, 0.f);
        float m3 = fmaxf(v.w + bv.w, 0.f);
        float* addr = g_agg + dst * 128 + lane * 4;
        asm volatile("red.global.add.v4.f32 [%0], {%1,%2,%3,%4};"
                     :: "l"(addr), "f"(m0), "f"(m1), "f"(m2), "f"(m3) : "memory");
    }
}

// Pre-convert weights to bf16 hi/lo; pack edge codes; zero stats; bias tile.
__global__ void convert_kernel(const float* __restrict__ w1, const float* __restrict__ w2,
                               const float* __restrict__ lin, const float* __restrict__ linb,
                               const int* __restrict__ ea) {
    int idx = blockIdx.x * 256 + threadIdx.x;
    if (idx < NE) {
        int a0 = __ldg(ea + 3 * idx), a1 = __ldg(ea + 3 * idx + 1), a2 = __ldg(ea + 3 * idx + 2);
        g_ecode[idx] = a0 | (a1 << 4) | (a2 << 8);
    }
    if (idx < 5 * 128 * 256) {
        float v = w1[idx];
        __nv_bfloat16 h = __float2bfloat16_rn(v);
        ((__nv_bfloat16*)g_w1h)[idx] = h;
        ((__nv_bfloat16*)g_w1l)[idx] = __float2bfloat16_rn(v - __bfloat162float(h));
        v = w2[idx];
        h = __float2bfloat16_rn(v);
        ((__nv_bfloat16*)g_w2h)[idx] = h;
        ((__nv_bfloat16*)g_w2l)[idx] = __float2bfloat16_rn(v - __bfloat162float(h));
    }
    if (idx < 128 * 256) {
        float v = lin[idx];
        __nv_bfloat16 h = __float2bfloat16_rn(v);
        ((__nv_bfloat16*)g_linh)[idx] = h;
        ((__nv_bfloat16*)g_linl)[idx] = __float2bfloat16_rn(v - __bfloat162float(h));
    }
    if (idx < 16 * 256) g_bias_tile[idx] = __ldg(linb + (idx & 255));
    if (idx < 512) g_stats1[idx] = 0.f;
    if (idx < 256) g_stats2[idx] = 0.f;
    if (idx < 2) g_cnt[idx] = 0u;
}

// Column stats + fused BN finalize (last-block-done). Self-resets stats & cnt.
template <int NC, int WHICH>
__global__ void stats_kernel(const float* __restrict__ gamma, const float* __restrict__ beta) {
    const float* src = (NC == 256) ? g_t : g_z2;
    float* st = (NC == 256) ? g_stats1 : g_stats2;
    int col = threadIdx.x;
    int r0 = blockIdx.x * 128;
    int rend = min(r0 + 128, NN);
    float s = 0.f, q = 0.f;
    for (int r = r0; r < rend; r++) {
        float v = src[(size_t)r * NC + col];
        s += v;
        q = fmaf(v, v, q);
    }
    atomicAdd(&st[col], s);
    atomicAdd(&st[NC + col], q);
    __threadfence();
    __shared__ unsigned done;
    if (threadIdx.x == 0) done = atomicAdd(&g_cnt[WHICH], 1u);
    __syncthreads();
    if (done == gridDim.x - 1) {
        float mu = st[col] * (1.f / NN);
        float var = st[NC + col] * (1.f / NN) - mu * mu;
        float sc = gamma[col] * rsqrtf(var + 1e-5f);
        float sh = beta[col] - mu * sc;
        if (NC == 256) { g_bn1A[col] = sc; g_bn1B[col] = sh; }
        else           { g_bn2A[col] = sc; g_bn2B[col] = sh; }
        st[col] = 0.f;
        st[NC + col] = 0.f;
        if (col == 0) g_cnt[WHICH] = 0u;
    }
}

// Apply BN2 (+relu) h = act(bn2(z2)); also re-zeroes g_agg for next layer.
__global__ void bn_apply_kernel(int do_relu) {
    int idx = blockIdx.x * 256 + threadIdx.x;
    float4 v = ((const float4*)g_z2)[idx];
    int c = (idx & 31) * 4;
    v.x = fmaf(g_bn2A[c + 0], v.x, g_bn2B[c + 0]);
    v.y = fmaf(g_bn2A[c + 1], v.y, g_bn2B[c + 1]);
    v.z = fmaf(g_bn2A[c + 2], v.z, g_bn2B[c + 2]);
    v.w = fmaf(g_bn2A[c + 3], v.w, g_bn2B[c + 3]);
    if (do_relu) {
        v.x = fmaxf(v.x, 0.f); v.y = fmaxf(v.y, 0.f);
        v.z = fmaxf(v.z, 0.f); v.w = fmaxf(v.w, 0.f);
    }
    ((float4*)g_h)[idx] = v;
    ((float4*)g_agg)[idx] = make_float4(0.f, 0.f, 0.f, 0.f);  // fused zero
}

// ----------------------- bf16x3 WMMA GEMM (tensor pipe) ---------------------
// CTA tile 128x128, 8 warps (2x4), warp tile 64x32, 2 CTAs/SM (<=128 regs).
// BK=32 double-buffered; B via cp.async; A fused-converted to bf16 hi/lo.
// MODE 0: A=(1+eps)*h+agg, B=w1  -> g_t       (grid.y = 2)
// MODE 1: A=relu(bn1(g_t)), B=w2 -> g_z2      (grid.y = 1)
// MODE 2: A=h, B=lin, acc preloaded with lin_b tile -> out (grid.y = 2)
template <int KD, int MODE>
__device__ __forceinline__ float4 loadA(int grow, int k, float epsv) {
    float4 v = make_float4(0.f, 0.f, 0.f, 0.f);
    if (grow < NN) {
        int gi = (grow * KD + k) >> 2;
        if (MODE == 0) {
            float4 a = ((const float4*)g_h)[gi];
            float4 b = ((const float4*)g_agg)[gi];
            v.x = fmaf(epsv, a.x, b.x);
            v.y = fmaf(epsv, a.y, b.y);
            v.z = fmaf(epsv, a.z, b.z);
            v.w = fmaf(epsv, a.w, b.w);
        } else if (MODE == 1) {
            float4 a = ((const float4*)g_t)[gi];
            v.x = fmaxf(fmaf(g_bn1A[k + 0], a.x, g_bn1B[k + 0]), 0.f);
            v.y = fmaxf(fmaf(g_bn1A[k + 1], a.y, g_bn1B[k + 1]), 0.f);
            v.z = fmaxf(fmaf(g_bn1A[k + 2], a.z, g_bn1B[k + 2]), 0.f);
            v.w = fmaxf(fmaf(g_bn1A[k + 3], a.w, g_bn1B[k + 3]), 0.f);
        } else {
            v = ((const float4*)g_h)[gi];
        }
    }
    return v;
}

__device__ __forceinline__ void cvt_split4(float4 v, uint2& hi, uint2& lo) {
    __nv_bfloat16 hx = __float2bfloat16_rn(v.x), hy = __float2bfloat16_rn(v.y);
    __nv_bfloat16 hz = __float2bfloat16_rn(v.z), hw = __float2bfloat16_rn(v.w);
    __nv_bfloat162 h01, h23, l01, l23;
    h01.x = hx; h01.y = hy; h23.x = hz; h23.y = hw;
    l01.x = __float2bfloat16_rn(v.x - __bfloat162float(hx));
    l01.y = __float2bfloat16_rn(v.y - __bfloat162float(hy));
    l23.x = __float2bfloat16_rn(v.z - __bfloat162float(hz));
    l23.y = __float2bfloat16_rn(v.w - __bfloat162float(hw));
    hi.x = *(uint32_t*)&h01; hi.y = *(uint32_t*)&h23;
    lo.x = *(uint32_t*)&l01; lo.y = *(uint32_t*)&l23;
}

// A: 2 stages x (hi+lo) x 128x40 bf16 = 40960 B; B: 2 stages x (hi+lo) x 32x136 bf16 = 34816 B
#define ASTG (128 * 40 * 2)
#define BSTG (32 * 136 * 2)
#define AH_ 0
#define AL_ (2 * ASTG)
#define BH_ (4 * ASTG)
#define BL_ (4 * ASTG + 2 * BSTG)
#define GEMM_SMEM (4 * ASTG + 4 * BSTG)

template <int KD, int NC, int MODE>
__global__ void __launch_bounds__(256, 2)
mma_gemm(int layer, float* __restrict__ outP, const float* __restrict__ epsp) {
    extern __shared__ char sm[];
    constexpr int NCH = KD / 32;

    int tid = threadIdx.x;
    int row0 = blockIdx.x * 128;
    int n0 = blockIdx.y * 128;
    int wid = tid >> 5;
    int wm = wid >> 2, wn = wid & 3;   // warp tile 64x32

    float epsv = (MODE == 0) ? 1.f + __ldg(epsp + layer) : 0.f;
    const uint4* WH = (MODE == 0) ? g_w1h + layer * 4096
                    : (MODE == 1) ? g_w2h + layer * 4096 : g_linh;
    const uint4* WL = (MODE == 0) ? g_w1l + layer * 4096
                    : (MODE == 1) ? g_w2l + layer * 4096 : g_linl;

    wmma::fragment<wmma::accumulator, 16, 16, 16, float> acc[4][2];
#pragma unroll
    for (int i = 0; i < 4; i++)
#pragma unroll
        for (int j = 0; j < 2; j++) {
            if (MODE == 2)
                wmma::load_matrix_sync(acc[i][j], g_bias_tile + n0 + wn * 32 + j * 16, 256,
                                       wmma::mem_row_major);
            else
                wmma::fill_fragment(acc[i][j], 0.f);
        }

    float4 pa[4];

    auto prefetchA = [&](int ch) {
#pragma unroll
        for (int q = 0; q < 4; q++) {
            int fi = q * 256 + tid;
            pa[q] = loadA<KD, MODE>(row0 + (fi >> 3), ch * 32 + (fi & 7) * 4, epsv);
        }
    };
    auto storeA = [&](int st) {
#pragma unroll
        for (int q = 0; q < 4; q++) {
            int fi = q * 256 + tid;
            int row = fi >> 3, k = (fi & 7) * 4;
            uint2 hi, lo;
            cvt_split4(pa[q], hi, lo);
            *(uint2*)(sm + AH_ + st * ASTG + (row * 40 + k) * 2) = hi;
            *(uint2*)(sm + AL_ + st * ASTG + (row * 40 + k) * 2) = lo;
        }
    };
    auto loadB = [&](int ch, int st) {
        // B tile 32x128 bf16 per table: 512 uint4 / 256 threads = 2 each
#pragma unroll
        for (int u = 0; u < 2; u++) {
            int ui = u * 256 + tid;
            int row = ui >> 4, cb = (ui & 15) * 8;
            int gi = ((ch * 32 + row) * NC + n0 + cb) >> 3;
            cp16(sm + BH_ + st * BSTG + (row * 136 + cb) * 2, WH + gi);
            cp16(sm + BL_ + st * BSTG + (row * 136 + cb) * 2, WL + gi);
        }
        cp_commit();
    };

    prefetchA(0);
    loadB(0, 0);
    storeA(0);
    cp_wait0();
    __syncthreads();

    for (int ch = 0; ch < NCH; ch++) {
        int st = ch & 1;
        if (ch + 1 < NCH) {
            loadB(ch + 1, st ^ 1);
            prefetchA(ch + 1);
        }
        const __nv_bfloat16* Ah = (const __nv_bfloat16*)(sm + AH_ + st * ASTG);
        const __nv_bfloat16* Al = (const __nv_bfloat16*)(sm + AL_ + st * ASTG);
        const __nv_bfloat16* Bh = (const __nv_bfloat16*)(sm + BH_ + st * BSTG);
        const __nv_bfloat16* Bl = (const __nv_bfloat16*)(sm + BL_ + st * BSTG);

#pragma unroll
        for (int kk = 0; kk < 32; kk += 16) {
            wmma::fragment<wmma::matrix_b, 16, 16, 16, __nv_bfloat16, wmma::row_major> bh[2], bl[2];
#pragma unroll
            for (int j = 0; j < 2; j++) {
                wmma::load_matrix_sync(bh[j], Bh + kk * 136 + wn * 32 + j * 16, 136);
                wmma::load_matrix_sync(bl[j], Bl + kk * 136 + wn * 32 + j * 16, 136);
            }
            wmma::fragment<wmma::matrix_a, 16, 16, 16, __nv_bfloat16, wmma::row_major> af;
#pragma unroll
            for (int i = 0; i < 4; i++) {
                wmma::load_matrix_sync(af, Ah + (wm * 64 + i * 16) * 40 + kk, 40);
#pragma unroll
                for (int j = 0; j < 2; j++) wmma::mma_sync(acc[i][j], af, bh[j], acc[i][j]);
#pragma unroll
                for (int j = 0; j < 2; j++) wmma::mma_sync(acc[i][j], af, bl[j], acc[i][j]);
            }
#pragma unroll
            for (int i = 0; i < 4; i++) {
                wmma::load_matrix_sync(af, Al + (wm * 64 + i * 16) * 40 + kk, 40);
#pragma unroll
                for (int j = 0; j < 2; j++) wmma::mma_sync(acc[i][j], af, bh[j], acc[i][j]);
            }
        }
        if (ch + 1 < NCH) {
            storeA(st ^ 1);
            cp_wait0();
            __syncthreads();
        }
    }

    // epilogue: NN % 64 == 0, warp-tile rows 64-aligned -> all-or-none guard
    int mrow = row0 + wm * 64;
    if (mrow < NN) {
#pragma unroll
        for (int i = 0; i < 4; i++) {
            int r = mrow + i * 16;
            float* dst;
            if (MODE == 0)      dst = g_t + (size_t)r * 256 + n0;
            else if (MODE == 1) dst = g_z2 + (size_t)r * 128;
            else                dst = outP + (size_t)r * 256 + n0;
#pragma unroll
            for (int j = 0; j < 2; j++)
                wmma::store_matrix_sync(dst + wn * 32 + j * 16, acc[i][j], NC,
                                        wmma::mem_row_major);
        }
    }
}

// ---------------------------------------------------------------------------
extern "C" void kernel_launch(void* const* d_in, const int* in_sizes, int n_in,
                              void* d_out, int out_size) {
    const int*   x    = (const int*)d_in[0];
    const int*   ei   = (const int*)d_in[1];
    const int*   ea   = (const int*)d_in[2];
    const float* aemb = (const float*)d_in[3];
    const float* bemb = (const float*)d_in[4];
    const float* eps  = (const float*)d_in[5];
    const float* w1   = (const float*)d_in[6];
    const float* bn1g = (const float*)d_in[8];
    const float* bn1b = (const float*)d_in[9];
    const float* w2   = (const float*)d_in[10];
    const float* bng  = (const float*)d_in[12];
    const float* bnb  = (const float*)d_in[13];
    const float* linw = (const float*)d_in[14];
    const float* linb = (const float*)d_in[15];

    cudaFuncSetAttribute(mma_gemm<128, 256, 0>, cudaFuncAttributeMaxDynamicSharedMemorySize, GEMM_SMEM);
    cudaFuncSetAttribute(mma_gemm<256, 128, 1>, cudaFuncAttributeMaxDynamicSharedMemorySize, GEMM_SMEM);
    cudaFuncSetAttribute(mma_gemm<128, 256, 2>, cudaFuncAttributeMaxDynamicSharedMemorySize, GEMM_SMEM);

    convert_kernel<<<2500, 256>>>(w1, w2, linw, linb, ea);
    atom_kernel<<<5000, 256>>>(x, aemb);
    for (int l = 0; l < 5; l++) {
        bond_combo_kernel<<<512, 256>>>(bemb + l * 3 * 16 * 128);
        edge_kernel<<<5000, 256>>>(ei);
        mma_gemm<128, 256, 0><<<dim3(313, 2), 256, GEMM_SMEM>>>(l, nullptr, eps);
        stats_kernel<256, 0><<<313, 256>>>(bn1g + l * 256, bn1b + l * 256);
        mma_gemm<256, 128, 1><<<dim3(313, 1), 256, GEMM_SMEM>>>(l, nullptr, nullptr);
        stats_kernel<128, 1><<<313, 128>>>(bng + l * 128, bnb + l * 128);
        bn_apply_kernel<<<5000, 256>>>(l < 4 ? 1 : 0);
    }
    mma_gemm<128, 256, 2><<<dim3(313, 2), 256, GEMM_SMEM>>>(0, (float*)d_out, nullptr);
}

// round 17
// speedup vs baseline: 1.8135x; 1.0784x over previous
#include <cuda_runtime.h>
#include <cuda_bf16.h>
#include <mma.h>
#include <cstdint>

using namespace nvcuda;

#define NN 40000
#define NE 640000

// ------------------------- scratch (device globals) -------------------------
__device__ float g_h[NN * 128];
__device__ float g_agg[NN * 128];          // holds z = (1+eps)h + agg after edge pass
__device__ float g_t[NN * 256];
__device__ float g_z2[NN * 128];
__device__ float g_stats1[512];
__device__ float g_stats2[256];
__device__ float g_bn1A[256], g_bn1B[256];
__device__ float g_bn2A[128], g_bn2B[128];
__device__ unsigned g_cnt[2];
__device__ float g_bias_tile[16 * 256];    // 16 identical rows of lin_b
__device__ int g_ecode[NE];                // packed (a0,a1,a2) per edge (unsorted)
__device__ float g_bcombo[4096 * 128];     // per-layer bond-combo table
// CSR sort-by-dst structures (rebuilt every call; edge list is layer-invariant)
__device__ unsigned g_deg[NN];
__device__ unsigned g_off[NN + 1];
__device__ unsigned g_pos[NN];
__device__ unsigned g_esorted[NE];         // src | code<<16
// bf16 hi/lo weights, natural [k][n] layout (row-major matrix_b)
__device__ uint4 g_w1h[5 * 128 * 256 / 8], g_w1l[5 * 128 * 256 / 8];
__device__ uint4 g_w2h[5 * 256 * 128 / 8], g_w2l[5 * 256 * 128 / 8];
__device__ uint4 g_linh[128 * 256 / 8],    g_linl[128 * 256 / 8];

// ------------------------------ PTX helpers --------------------------------
__device__ __forceinline__ uint32_t s2u(const void* p) {
    uint32_t a;
    asm("{ .reg .u64 t; cvta.to.shared.u64 t, %1; cvt.u32.u64 %0, t; }" : "=r"(a) : "l"(p));
    return a;
}
__device__ __forceinline__ void cp16(void* smem_dst, const void* gsrc) {
    asm volatile("cp.async.cg.shared.global [%0], [%1], 16;"
                 :: "r"(s2u(smem_dst)), "l"(gsrc) : "memory");
}
__device__ __forceinline__ void cp_commit() {
    asm volatile("cp.async.commit_group;" ::: "memory");
}
__device__ __forceinline__ void cp_wait0() {
    asm volatile("cp.async.wait_group 0;" ::: "memory");
}

// ------------------------------ preamble kernels ----------------------------
__global__ void zero_deg_kernel() {
    int i = blockIdx.x * 256 + threadIdx.x;
    if (i < NN) g_deg[i] = 0u;
}

// Pack edge codes + dst histogram; weights to bf16 hi/lo; bias tile; stat zero.
__global__ void convert_kernel(const float* __restrict__ w1, const float* __restrict__ w2,
                               const float* __restrict__ lin, const float* __restrict__ linb,
                               const int* __restrict__ ea, const int* __restrict__ ei) {
    int idx = blockIdx.x * 256 + threadIdx.x;
    if (idx < NE) {
        int a0 = __ldg(ea + 3 * idx), a1 = __ldg(ea + 3 * idx + 1), a2 = __ldg(ea + 3 * idx + 2);
        g_ecode[idx] = a0 | (a1 << 4) | (a2 << 8);
        atomicAdd(&g_deg[__ldg(ei + NE + idx)], 1u);
    }
    if (idx < 5 * 128 * 256) {
        float v = w1[idx];
        __nv_bfloat16 h = __float2bfloat16_rn(v);
        ((__nv_bfloat16*)g_w1h)[idx] = h;
        ((__nv_bfloat16*)g_w1l)[idx] = __float2bfloat16_rn(v - __bfloat162float(h));
        v = w2[idx];
        h = __float2bfloat16_rn(v);
        ((__nv_bfloat16*)g_w2h)[idx] = h;
        ((__nv_bfloat16*)g_w2l)[idx] = __float2bfloat16_rn(v - __bfloat162float(h));
    }
    if (idx < 128 * 256) {
        float v = lin[idx];
        __nv_bfloat16 h = __float2bfloat16_rn(v);
        ((__nv_bfloat16*)g_linh)[idx] = h;
        ((__nv_bfloat16*)g_linl)[idx] = __float2bfloat16_rn(v - __bfloat162float(h));
    }
    if (idx < 16 * 256) g_bias_tile[idx] = __ldg(linb + (idx & 255));
    if (idx < 512) g_stats1[idx] = 0.f;
    if (idx < 256) g_stats2[idx] = 0.f;
    if (idx < 2) g_cnt[idx] = 0u;
}

// Exclusive prefix sum of g_deg -> g_off / g_pos. One block, 1024 threads.
__global__ void scan_kernel() {
    __shared__ unsigned ssum[1024];
    int t = threadIdx.x;
    int i0 = t * 40, i1 = min(i0 + 40, NN);
    unsigned s = 0;
    for (int i = i0; i < i1; i++) s += g_deg[i];
    ssum[t] = s;
    __syncthreads();
    for (int d = 1; d < 1024; d <<= 1) {
        unsigned v = (t >= d) ? ssum[t - d] : 0u;
        __syncthreads();
        ssum[t] += v;
        __syncthreads();
    }
    unsigned base = (t == 0) ? 0u : ssum[t - 1];
    for (int i = i0; i < i1; i++) {
        g_off[i] = base;
        g_pos[i] = base;
        base += g_deg[i];
    }
    if (t == 1023) g_off[NN] = NE;
}

__global__ void scatter_kernel(const int* __restrict__ ei) {
    int e = blockIdx.x * 256 + threadIdx.x;
    if (e >= NE) return;
    unsigned src = (unsigned)__ldg(ei + e);
    int dst = __ldg(ei + NE + e);
    unsigned p = atomicAdd(&g_pos[dst], 1u);
    g_esorted[p] = src | ((unsigned)g_ecode[e] << 16);
}

// ------------------------------ small kernels ------------------------------
__global__ void atom_kernel(const int* __restrict__ x, const float* __restrict__ aemb) {
    int gwarp = (blockIdx.x * 256 + threadIdx.x) >> 5;
    int lane = threadIdx.x & 31;
    if (gwarp >= NN) return;
    const float4* ae = (const float4*)aemb;
    float4 acc = make_float4(0.f, 0.f, 0.f, 0.f);
#pragma unroll
    for (int f = 0; f < 9; f++) {
        int idx = __ldg(x + gwarp * 9 + f);
        float4 v = ae[(f * 128 + idx) * 32 + lane];
        acc.x += v.x; acc.y += v.y; acc.z += v.z; acc.w += v.w;
    }
    ((float4*)g_h)[gwarp * 32 + lane] = acc;
}

// Build the 4096-combo bond table: bcombo[code] = b0[a0]+b1[a1]+b2[a2]
__global__ void bond_combo_kernel(const float* __restrict__ bond) {
    int idx = blockIdx.x * 256 + threadIdx.x;   // over 4096*32 float4
    int code = idx >> 5, c4 = idx & 31;
    int a0 = code & 15, a1 = (code >> 4) & 15, a2 = code >> 8;
    const float4* b4 = (const float4*)bond;
    float4 v0 = b4[a0 * 32 + c4];
    float4 v1 = b4[(16 + a1) * 32 + c4];
    float4 v2 = b4[(32 + a2) * 32 + c4];
    float4 o;
    o.x = v0.x + v1.x + v2.x;
    o.y = v0.y + v1.y + v2.y;
    o.z = v0.z + v1.z + v2.z;
    o.w = v0.w + v1.w + v2.w;
    ((float4*)g_bcombo)[idx] = o;
}

// One warp per dst node: z[node] = (1+eps)*h[node] + sum_e relu(h[src]+bcombo[code])
__global__ void edge_kernel(const float* __restrict__ epsp, int layer) {
    int node = (blockIdx.x * 256 + threadIdx.x) >> 5;
    int lane = threadIdx.x & 31;
    if (node >= NN) return;
    unsigned e = g_off[node], e1 = g_off[node + 1];
    const float4* h4 = (const float4*)g_h;
    const float4* bc4 = (const float4*)g_bcombo;
    float4 acc = make_float4(0.f, 0.f, 0.f, 0.f);
    // 4-wide unroll for MLP
    for (; e + 4 <= e1; e += 4) {
        unsigned p0 = __ldg(g_esorted + e + 0);
        unsigned p1 = __ldg(g_esorted + e + 1);
        unsigned p2 = __ldg(g_esorted + e + 2);
        unsigned p3 = __ldg(g_esorted + e + 3);
        float4 v0 = h4[(p0 & 0xFFFF) * 32 + lane];
        float4 b0 = bc4[(p0 >> 16) * 32 + lane];
        float4 v1 = h4[(p1 & 0xFFFF) * 32 + lane];
        float4 b1 = bc4[(p1 >> 16) * 32 + lane];
        float4 v2 = h4[(p2 & 0xFFFF) * 32 + lane];
        float4 b2 = bc4[(p2 >> 16) * 32 + lane];
        float4 v3 = h4[(p3 & 0xFFFF) * 32 + lane];
        float4 b3 = bc4[(p3 >> 16) * 32 + lane];
        acc.x += fmaxf(v0.x + b0.x, 0.f) + fmaxf(v1.x + b1.x, 0.f) +
                 fmaxf(v2.x + b2.x, 0.f) + fmaxf(v3.x + b3.x, 0.f);
        acc.y += fmaxf(v0.y + b0.y, 0.f) + fmaxf(v1.y + b1.y, 0.f) +
                 fmaxf(v2.y + b2.y, 0.f) + fmaxf(v3.y + b3.y, 0.f);
        acc.z += fmaxf(v0.z + b0.z, 0.f) + fmaxf(v1.z + b1.z, 0.f) +
                 fmaxf(v2.z + b2.z, 0.f) + fmaxf(v3.z + b3.z, 0.f);
        acc.w += fmaxf(v0.w + b0.w, 0.f) + fmaxf(v1.w + b1.w, 0.f) +
                 fmaxf(v2.w + b2.w, 0.f) + fmaxf(v3.w + b3.w, 0.f);
    }
    for (; e < e1; e++) {
        unsigned p = __ldg(g_esorted + e);
        float4 v = h4[(p & 0xFFFF) * 32 + lane];
        float4 b = bc4[(p >> 16) * 32 + lane];
        acc.x += fmaxf(v.x + b.x, 0.f);
        acc.y += fmaxf(v.y + b.y, 0.f);
        acc.z += fmaxf(v.z + b.z, 0.f);
        acc.w += fmaxf(v.w + b.w, 0.f);
    }
    float epsv = 1.f + __ldg(epsp + layer);
    float4 hv = h4[node * 32 + lane];
    acc.x = fmaf(epsv, hv.x, acc.x);
    acc.y = fmaf(epsv, hv.y, acc.y);
    acc.z = fmaf(epsv, hv.z, acc.z);
    acc.w = fmaf(epsv, hv.w, acc.w);
    ((float4*)g_agg)[node * 32 + lane] = acc;
}

// Column stats + fused BN finalize (last-block-done). Self-resets stats & cnt.
template <int NC, int WHICH>
__global__ void stats_kernel(const float* __restrict__ gamma, const float* __restrict__ beta) {
    const float* src = (NC == 256) ? g_t : g_z2;
    float* st = (NC == 256) ? g_stats1 : g_stats2;
    int col = threadIdx.x;
    int r0 = blockIdx.x * 128;
    int rend = min(r0 + 128, NN);
    float s = 0.f, q = 0.f;
    for (int r = r0; r < rend; r++) {
        float v = src[(size_t)r * NC + col];
        s += v;
        q = fmaf(v, v, q);
    }
    atomicAdd(&st[col], s);
    atomicAdd(&st[NC + col], q);
    __threadfence();
    __shared__ unsigned done;
    if (threadIdx.x == 0) done = atomicAdd(&g_cnt[WHICH], 1u);
    __syncthreads();
    if (done == gridDim.x - 1) {
        float mu = st[col] * (1.f / NN);
        float var = st[NC + col] * (1.f / NN) - mu * mu;
        float sc = gamma[col] * rsqrtf(var + 1e-5f);
        float sh = beta[col] - mu * sc;
        if (NC == 256) { g_bn1A[col] = sc; g_bn1B[col] = sh; }
        else           { g_bn2A[col] = sc; g_bn2B[col] = sh; }
        st[col] = 0.f;
        st[NC + col] = 0.f;
        if (col == 0) g_cnt[WHICH] = 0u;
    }
}

// Apply BN2 (+relu): h = act(bn2(z2)).
__global__ void bn_apply_kernel(int do_relu) {
    int idx = blockIdx.x * 256 + threadIdx.x;
    float4 v = ((const float4*)g_z2)[idx];
    int c = (idx & 31) * 4;
    v.x = fmaf(g_bn2A[c + 0], v.x, g_bn2B[c + 0]);
    v.y = fmaf(g_bn2A[c + 1], v.y, g_bn2B[c + 1]);
    v.z = fmaf(g_bn2A[c + 2], v.z, g_bn2B[c + 2]);
    v.w = fmaf(g_bn2A[c + 3], v.w, g_bn2B[c + 3]);
    if (do_relu) {
        v.x = fmaxf(v.x, 0.f); v.y = fmaxf(v.y, 0.f);
        v.z = fmaxf(v.z, 0.f); v.w = fmaxf(v.w, 0.f);
    }
    ((float4*)g_h)[idx] = v;
}

// ----------------------- bf16x3 WMMA GEMM (tensor pipe) ---------------------
// CTA tile 128x128, 8 warps (2x4), warp tile 64x32, 2 CTAs/SM.
// MODE 0: A=g_agg (z precomputed), B=w1 -> g_t      (grid.y = 2)
// MODE 1: A=relu(bn1(g_t)), B=w2 -> g_z2            (grid.y = 1)
// MODE 2: A=g_h, B=lin, acc preloaded with lin_b -> out (grid.y = 2)
template <int KD, int MODE>
__device__ __forceinline__ float4 loadA(int grow, int k) {
    float4 v = make_float4(0.f, 0.f, 0.f, 0.f);
    if (grow < NN) {
        int gi = (grow * KD + k) >> 2;
        if (MODE == 0) {
            v = ((const float4*)g_agg)[gi];
        } else if (MODE == 1) {
            float4 a = ((const float4*)g_t)[gi];
            v.x = fmaxf(fmaf(g_bn1A[k + 0], a.x, g_bn1B[k + 0]), 0.f);
            v.y = fmaxf(fmaf(g_bn1A[k + 1], a.y, g_bn1B[k + 1]), 0.f);
            v.z = fmaxf(fmaf(g_bn1A[k + 2], a.z, g_bn1B[k + 2]), 0.f);
            v.w = fmaxf(fmaf(g_bn1A[k + 3], a.w, g_bn1B[k + 3]), 0.f);
        } else {
            v = ((const float4*)g_h)[gi];
        }
    }
    return v;
}

__device__ __forceinline__ void cvt_split4(float4 v, uint2& hi, uint2& lo) {
    __nv_bfloat16 hx = __float2bfloat16_rn(v.x), hy = __float2bfloat16_rn(v.y);
    __nv_bfloat16 hz = __float2bfloat16_rn(v.z), hw = __float2bfloat16_rn(v.w);
    __nv_bfloat162 h01, h23, l01, l23;
    h01.x = hx; h01.y = hy; h23.x = hz; h23.y = hw;
    l01.x = __float2bfloat16_rn(v.x - __bfloat162float(hx));
    l01.y = __float2bfloat16_rn(v.y - __bfloat162float(hy));
    l23.x = __float2bfloat16_rn(v.z - __bfloat162float(hz));
    l23.y = __float2bfloat16_rn(v.w - __bfloat162float(hw));
    hi.x = *(uint32_t*)&h01; hi.y = *(uint32_t*)&h23;
    lo.x = *(uint32_t*)&l01; lo.y = *(uint32_t*)&l23;
}

#define ASTG (128 * 40 * 2)
#define BSTG (32 * 136 * 2)
#define AH_ 0
#define AL_ (2 * ASTG)
#define BH_ (4 * ASTG)
#define BL_ (4 * ASTG + 2 * BSTG)
#define GEMM_SMEM (4 * ASTG + 4 * BSTG)

template <int KD, int NC, int MODE>
__global__ void __launch_bounds__(256, 2)
mma_gemm(int layer, float* __restrict__ outP) {
    extern __shared__ char sm[];
    constexpr int NCH = KD / 32;

    int tid = threadIdx.x;
    int row0 = blockIdx.x * 128;
    int n0 = blockIdx.y * 128;
    int wid = tid >> 5;
    int wm = wid >> 2, wn = wid & 3;   // warp tile 64x32

    const uint4* WH = (MODE == 0) ? g_w1h + layer * 4096
                    : (MODE == 1) ? g_w2h + layer * 4096 : g_linh;
    const uint4* WL = (MODE == 0) ? g_w1l + layer * 4096
                    : (MODE == 1) ? g_w2l + layer * 4096 : g_linl;

    wmma::fragment<wmma::accumulator, 16, 16, 16, float> acc[4][2];
#pragma unroll
    for (int i = 0; i < 4; i++)
#pragma unroll
        for (int j = 0; j < 2; j++) {
            if (MODE == 2)
                wmma::load_matrix_sync(acc[i][j], g_bias_tile + n0 + wn * 32 + j * 16, 256,
                                       wmma::mem_row_major);
            else
                wmma::fill_fragment(acc[i][j], 0.f);
        }

    float4 pa[4];

    auto prefetchA = [&](int ch) {
#pragma unroll
        for (int q = 0; q < 4; q++) {
            int fi = q * 256 + tid;
            pa[q] = loadA<KD, MODE>(row0 + (fi >> 3), ch * 32 + (fi & 7) * 4);
        }
    };
    auto storeA = [&](int st) {
#pragma unroll
        for (int q = 0; q < 4; q++) {
            int fi = q * 256 + tid;
            int row = fi >> 3, k = (fi & 7) * 4;
            uint2 hi, lo;
            cvt_split4(pa[q], hi, lo);
            *(uint2*)(sm + AH_ + st * ASTG + (row * 40 + k) * 2) = hi;
            *(uint2*)(sm + AL_ + st * ASTG + (row * 40 + k) * 2) = lo;
        }
    };
    auto loadB = [&](int ch, int st) {
#pragma unroll
        for (int u = 0; u < 2; u++) {
            int ui = u * 256 + tid;
            int row = ui >> 4, cb = (ui & 15) * 8;
            int gi = ((ch * 32 + row) * NC + n0 + cb) >> 3;
            cp16(sm + BH_ + st * BSTG + (row * 136 + cb) * 2, WH + gi);
            cp16(sm + BL_ + st * BSTG + (row * 136 + cb) * 2, WL + gi);
        }
        cp_commit();
    };

    prefetchA(0);
    loadB(0, 0);
    storeA(0);
    cp_wait0();
    __syncthreads();

    for (int ch = 0; ch < NCH; ch++) {
        int st = ch & 1;
        if (ch + 1 < NCH) {
            loadB(ch + 1, st ^ 1);
            prefetchA(ch + 1);
        }
        const __nv_bfloat16* Ah = (const __nv_bfloat16*)(sm + AH_ + st * ASTG);
        const __nv_bfloat16* Al = (const __nv_bfloat16*)(sm + AL_ + st * ASTG);
        const __nv_bfloat16* Bh = (const __nv_bfloat16*)(sm + BH_ + st * BSTG);
        const __nv_bfloat16* Bl = (const __nv_bfloat16*)(sm + BL_ + st * BSTG);

#pragma unroll
        for (int kk = 0; kk < 32; kk += 16) {
            wmma::fragment<wmma::matrix_b, 16, 16, 16, __nv_bfloat16, wmma::row_major> bh[2], bl[2];
#pragma unroll
            for (int j = 0; j < 2; j++) {
                wmma::load_matrix_sync(bh[j], Bh + kk * 136 + wn * 32 + j * 16, 136);
                wmma::load_matrix_sync(bl[j], Bl + kk * 136 + wn * 32 + j * 16, 136);
            }
            wmma::fragment<wmma::matrix_a, 16, 16, 16, __nv_bfloat16, wmma::row_major> af;
#pragma unroll
            for (int i = 0; i < 4; i++) {
                wmma::load_matrix_sync(af, Ah + (wm * 64 + i * 16) * 40 + kk, 40);
#pragma unroll
                for (int j = 0; j < 2; j++) wmma::mma_sync(acc[i][j], af, bh[j], acc[i][j]);
#pragma unroll
                for (int j = 0; j < 2; j++) wmma::mma_sync(acc[i][j], af, bl[j], acc[i][j]);
            }
#pragma unroll
            for (int i = 0; i < 4; i++) {
                wmma::load_matrix_sync(af, Al + (wm * 64 + i * 16) * 40 + kk, 40);
#pragma unroll
                for (int j = 0; j < 2; j++) wmma::mma_sync(acc[i][j], af, bh[j], acc[i][j]);
            }
        }
        if (ch + 1 < NCH) {
            storeA(st ^ 1);
            cp_wait0();
            __syncthreads();
        }
    }

    int mrow = row0 + wm * 64;
    if (mrow < NN) {
#pragma unroll
        for (int i = 0; i < 4; i++) {
            int r = mrow + i * 16;
            float* dst;
            if (MODE == 0)      dst = g_t + (size_t)r * 256 + n0;
            else if (MODE == 1) dst = g_z2 + (size_t)r * 128;
            else                dst = outP + (size_t)r * 256 + n0;
#pragma unroll
            for (int j = 0; j < 2; j++)
                wmma::store_matrix_sync(dst + wn * 32 + j * 16, acc[i][j], NC,
                                        wmma::mem_row_major);
        }
    }
}

// ---------------------------------------------------------------------------
extern "C" void kernel_launch(void* const* d_in, const int* in_sizes, int n_in,
                              void* d_out, int out_size) {
    const int*   x    = (const int*)d_in[0];
    const int*   ei   = (const int*)d_in[1];
    const int*   ea   = (const int*)d_in[2];
    const float* aemb = (const float*)d_in[3];
    const float* bemb = (const float*)d_in[4];
    const float* eps  = (const float*)d_in[5];
    const float* w1   = (const float*)d_in[6];
    const float* bn1g = (const float*)d_in[8];
    const float* bn1b = (const float*)d_in[9];
    const float* w2   = (const float*)d_in[10];
    const float* bng  = (const float*)d_in[12];
    const float* bnb  = (const float*)d_in[13];
    const float* linw = (const float*)d_in[14];
    const float* linb = (const float*)d_in[15];

    cudaFuncSetAttribute(mma_gemm<128, 256, 0>, cudaFuncAttributeMaxDynamicSharedMemorySize, GEMM_SMEM);
    cudaFuncSetAttribute(mma_gemm<256, 128, 1>, cudaFuncAttributeMaxDynamicSharedMemorySize, GEMM_SMEM);
    cudaFuncSetAttribute(mma_gemm<128, 256, 2>, cudaFuncAttributeMaxDynamicSharedMemorySize, GEMM_SMEM);

    // Preamble: CSR sort by dst + weight conversion (once per call)
    zero_deg_kernel<<<157, 256>>>();
    convert_kernel<<<2500, 256>>>(w1, w2, linw, linb, ea, ei);
    scan_kernel<<<1, 1024>>>();
    scatter_kernel<<<2500, 256>>>(ei);
    atom_kernel<<<5000, 256>>>(x, aemb);

    for (int l = 0; l < 5; l++) {
        bond_combo_kernel<<<512, 256>>>(bemb + l * 3 * 16 * 128);
        edge_kernel<<<5000, 256>>>(eps, l);
        mma_gemm<128, 256, 0><<<dim3(313, 2), 256, GEMM_SMEM>>>(l, nullptr);
        stats_kernel<256, 0><<<313, 256>>>(bn1g + l * 256, bn1b + l * 256);
        mma_gemm<256, 128, 1><<<dim3(313, 1), 256, GEMM_SMEM>>>(l, nullptr);
        stats_kernel<128, 1><<<313, 128>>>(bng + l * 128, bnb + l * 128);
        bn_apply_kernel<<<5000, 256>>>(l < 4 ? 1 : 0);
    }
    mma_gemm<128, 256, 2><<<dim3(313, 2), 256, GEMM_SMEM>>>(0, (float*)d_out);
}